// round 2
// baseline (speedup 1.0000x reference)
#include <cuda_runtime.h>
#include <math.h>
#include <stdint.h>

#define BBATCH 64
#define NQD    32
#define NDD    512
#define DINF   64
#define DDF    128
#define KKN    16
#define NDN    (BBATCH*NDD)      // 32768
#define NQN    (BBATCH*NQD)      // 2048
#define EDM    (NDN*8)           // 262144
#define EQM    (NQN*8)           // 16384

// ------------------------- static device scratch ----------------------------
__device__ float g_dinv_d[NDN];
__device__ float g_dinv_q[NQN];
__device__ int   g_indeg_d[NDN];
__device__ int   g_indeg_q[NQN];
__device__ int   g_rows_d[NDN];
__device__ int   g_rows_q[NQN];
__device__ int   g_fill_d[NDN];
__device__ int   g_fill_q[NQN];
__device__ int   g_cols_d[EDM];
__device__ float g_vals_d[EDM];
__device__ int   g_cols_q[EQM];
__device__ float g_vals_q[EQM];
__device__ float g_xw[NDN*DDF];               // GEMM scratch (pre-aggregation h)
__device__ float g_hd[3*NDN*DDF];             // d1,d2,d3
__device__ float g_hq[3*NQN*DDF];             // q1,q2,q3
__device__ float g_dT[(size_t)BBATCH*DDF*NDD];// per-level d transposed [b][e][n]
__device__ float g_qw[(size_t)BBATCH*KKN*DDF*NQD]; // per-level qW [b][k][e][q]
__device__ float g_att[(size_t)BBATCH*NQD*NDD];
__device__ float g_lq[NQN*KKN];
__device__ float g_ld[NDN*KKN];
__device__ float g_e1[(size_t)BBATCH*NQD*NDD];
__device__ float g_e3[(size_t)BBATCH*NQD*NDD];
__device__ float g_acc[(size_t)BBATCH*NQD*NDD];
__device__ float g_wk[128];                   // folded weights

// ------------------------------ CSR build -----------------------------------
__global__ void zero2_kern(int* __restrict__ a, int* __restrict__ b, int n) {
    int i = blockIdx.x * blockDim.x + threadIdx.x;
    if (i < n) { a[i] = 0; b[i] = 0; }
}

__global__ void count_deg_kern(const int* __restrict__ dst, int E, int* __restrict__ indeg) {
    int e = blockIdx.x * blockDim.x + threadIdx.x;
    if (e < E) atomicAdd(&indeg[dst[e]], 1);
}

__global__ void dinv_kern(const int* __restrict__ indeg, float* __restrict__ dinv, int n) {
    int i = blockIdx.x * blockDim.x + threadIdx.x;
    if (i < n) dinv[i] = rsqrtf((float)indeg[i] + 1.0f);  // +1 for self loop
}

// per-graph exclusive scan of in-degree -> CSR row starts. blockDim == nper.
__global__ void scan_csr_kern(const int* __restrict__ indeg, int* __restrict__ rows,
                              int nper, int eper) {
    __shared__ int s[512];
    int g = blockIdx.x, t = threadIdx.x;
    int v = indeg[g * nper + t];
    s[t] = v; __syncthreads();
    for (int off = 1; off < blockDim.x; off <<= 1) {
        int x = (t >= off) ? s[t - off] : 0;
        __syncthreads();
        s[t] += x;
        __syncthreads();
    }
    rows[g * nper + t] = g * eper + s[t] - v;  // exclusive scan + graph base
}

__global__ void fill_csr_kern(const int* __restrict__ src, const int* __restrict__ dst, int E,
                              const float* __restrict__ dinv, const int* __restrict__ rows,
                              int* __restrict__ fill, int* __restrict__ cols,
                              float* __restrict__ vals) {
    int e = blockIdx.x * blockDim.x + threadIdx.x;
    if (e >= E) return;
    int s = src[e], t = dst[e];
    int p = atomicAdd(&fill[t], 1);
    int idx = rows[t] + p;
    cols[idx] = s;
    vals[idx] = dinv[s] * dinv[t];
}

// -------------------- SGEMM  C[M,128] = A[M,Kd] @ B[Kd,128] -----------------
__global__ __launch_bounds__(256) void sgemm_xw(const float* __restrict__ A,
                                                const float* __restrict__ B,
                                                float* __restrict__ C, int Kd) {
    __shared__ float As[8][128];
    __shared__ float Bs[8][128];
    const int m0 = blockIdx.x * 128;
    const int tid = threadIdx.x;
    const int ar = tid >> 1, ac = (tid & 1) * 4;
    const int br = tid >> 5, bc = (tid & 31) * 4;
    const int ty = tid >> 4, tx = tid & 15;
    float acc[8][8];
#pragma unroll
    for (int i = 0; i < 8; i++)
#pragma unroll
        for (int j = 0; j < 8; j++) acc[i][j] = 0.f;

    for (int k0 = 0; k0 < Kd; k0 += 8) {
        float4 a = *(const float4*)(A + (size_t)(m0 + ar) * Kd + k0 + ac);
        float4 bv = *(const float4*)(B + (size_t)(k0 + br) * 128 + bc);
        __syncthreads();
        As[ac + 0][ar] = a.x; As[ac + 1][ar] = a.y;
        As[ac + 2][ar] = a.z; As[ac + 3][ar] = a.w;
        *(float4*)&Bs[br][bc] = bv;
        __syncthreads();
#pragma unroll
        for (int kk = 0; kk < 8; kk++) {
            float4 a0 = *(float4*)&As[kk][ty * 8];
            float4 a1 = *(float4*)&As[kk][ty * 8 + 4];
            float4 b0 = *(float4*)&Bs[kk][tx * 8];
            float4 b1 = *(float4*)&Bs[kk][tx * 8 + 4];
            float av[8] = {a0.x,a0.y,a0.z,a0.w,a1.x,a1.y,a1.z,a1.w};
            float bw[8] = {b0.x,b0.y,b0.z,b0.w,b1.x,b1.y,b1.z,b1.w};
#pragma unroll
            for (int i = 0; i < 8; i++)
#pragma unroll
                for (int j = 0; j < 8; j++) acc[i][j] += av[i] * bw[j];
        }
    }
#pragma unroll
    for (int i = 0; i < 8; i++) {
        size_t row = (size_t)(m0 + ty * 8 + i) * 128;
        *(float4*)(C + row + tx * 8)     = make_float4(acc[i][0], acc[i][1], acc[i][2], acc[i][3]);
        *(float4*)(C + row + tx * 8 + 4) = make_float4(acc[i][4], acc[i][5], acc[i][6], acc[i][7]);
    }
}

// ------------------- GCN aggregation (warp per node) ------------------------
__global__ void spmm_gcn(const float* __restrict__ h, const int* __restrict__ rows,
                         const int* __restrict__ cols, const float* __restrict__ vals,
                         const int* __restrict__ indeg, const float* __restrict__ dinv,
                         const float* __restrict__ bias, float* __restrict__ out, int N) {
    int t = blockIdx.x * blockDim.x + threadIdx.x;
    int node = t >> 5, lane = t & 31;
    if (node >= N) return;
    float di = dinv[node];
    float self = di * di;
    float4 hv = *(const float4*)(h + (size_t)node * 128 + lane * 4);
    float ax = self * hv.x, ay = self * hv.y, az = self * hv.z, aw = self * hv.w;
    int r0 = rows[node], cnt = indeg[node];
    for (int e = 0; e < cnt; e++) {
        int s = __ldg(&cols[r0 + e]);
        float w = __ldg(&vals[r0 + e]);
        float4 n4 = *(const float4*)(h + (size_t)s * 128 + lane * 4);
        ax += w * n4.x; ay += w * n4.y; az += w * n4.z; aw += w * n4.w;
    }
    float4 b4 = *(const float4*)(bias + lane * 4);
    float4 o;
    o.x = fmaxf(ax + b4.x, 0.f); o.y = fmaxf(ay + b4.y, 0.f);
    o.z = fmaxf(az + b4.z, 0.f); o.w = fmaxf(aw + b4.w, 0.f);
    *(float4*)(out + (size_t)node * 128 + lane * 4) = o;
}

// -------------------------- transpose d -> dT --------------------------------
__global__ void transpose_dk(const float* __restrict__ d, float* __restrict__ dT) {
    __shared__ float ts[32][33];
    int b = blockIdx.z, n0 = blockIdx.y * 32, e0 = blockIdx.x * 32;
    int tx = threadIdx.x, ty = threadIdx.y;
#pragma unroll
    for (int j = 0; j < 32; j += 8)
        ts[ty + j][tx] = d[((size_t)b * 512 + n0 + ty + j) * 128 + e0 + tx];
    __syncthreads();
#pragma unroll
    for (int j = 0; j < 32; j += 8)
        dT[((size_t)b * 128 + e0 + ty + j) * 512 + n0 + tx] = ts[tx][ty + j];
}

// --------------- attention scores S = q @ dT (raw, scaled later) ------------
#define SG_SMEM ((16384 + 128*33) * 4)
__global__ __launch_bounds__(256) void s_gemm(const float* __restrict__ qf,
                                              const float* __restrict__ dT,
                                              float* __restrict__ S) {
    extern __shared__ float sm[];
    float* sd = sm;             // [128e][128n]
    float* sq = sm + 16384;     // [128e][33] padded, [e][q]
    const int b = blockIdx.y;
    const int n0 = blockIdx.x * 128;
    const int tid = threadIdx.x;
    const int tq = tid >> 5, tn = tid & 31;

    for (int i = tid; i < 4096; i += 256) {
        int e = i >> 5, c = i & 31;
        ((float4*)sd)[i] = *(const float4*)(dT + ((size_t)b * 128 + e) * 512 + n0 + c * 4);
    }
    for (int i = tid; i < 1024; i += 256) {
        int q = i >> 5, e4 = i & 31;
        float4 v = *(const float4*)(qf + ((size_t)b * 32 + q) * 128 + e4 * 4);
        sq[(e4 * 4 + 0) * 33 + q] = v.x;
        sq[(e4 * 4 + 1) * 33 + q] = v.y;
        sq[(e4 * 4 + 2) * 33 + q] = v.z;
        sq[(e4 * 4 + 3) * 33 + q] = v.w;
    }
    __syncthreads();
    float acc[4][4];
#pragma unroll
    for (int i = 0; i < 4; i++)
#pragma unroll
        for (int j = 0; j < 4; j++) acc[i][j] = 0.f;
#pragma unroll 2
    for (int e = 0; e < 128; e++) {
        float a0 = sq[e * 33 + tq * 4 + 0];
        float a1 = sq[e * 33 + tq * 4 + 1];
        float a2 = sq[e * 33 + tq * 4 + 2];
        float a3 = sq[e * 33 + tq * 4 + 3];
        float4 bv = *(float4*)(sd + e * 128 + tn * 4);
        acc[0][0] += a0*bv.x; acc[0][1] += a0*bv.y; acc[0][2] += a0*bv.z; acc[0][3] += a0*bv.w;
        acc[1][0] += a1*bv.x; acc[1][1] += a1*bv.y; acc[1][2] += a1*bv.z; acc[1][3] += a1*bv.w;
        acc[2][0] += a2*bv.x; acc[2][1] += a2*bv.y; acc[2][2] += a2*bv.z; acc[2][3] += a2*bv.w;
        acc[3][0] += a3*bv.x; acc[3][1] += a3*bv.y; acc[3][2] += a3*bv.z; acc[3][3] += a3*bv.w;
    }
#pragma unroll
    for (int i = 0; i < 4; i++) {
        size_t o = ((size_t)b * 32 + tq * 4 + i) * 512 + n0 + tn * 4;
        *(float4*)(S + o) = make_float4(acc[i][0], acc[i][1], acc[i][2], acc[i][3]);
    }
}

// --------------- qW[b,k,e,q] = sum_d q[b,q,d] Wn[k,d,e]  (transposed out) ---
__global__ __launch_bounds__(256) void qw_gemm(const float* __restrict__ qf,
                                               const float* __restrict__ Wn,
                                               float* __restrict__ out) {
    __shared__ float sq2[32 * 128];  // [q][d]
    __shared__ float sW[32 * 128];   // [dd][e]
    const int k = blockIdx.x, b = blockIdx.y;
    const int tid = threadIdx.x;
    const int tq = tid >> 5, tn = tid & 31;

    for (int i = tid; i < 1024; i += 256)
        ((float4*)sq2)[i] = ((const float4*)(qf + (size_t)b * 4096))[i];

    float acc[4][4];
#pragma unroll
    for (int i = 0; i < 4; i++)
#pragma unroll
        for (int j = 0; j < 4; j++) acc[i][j] = 0.f;

    for (int d0 = 0; d0 < 128; d0 += 32) {
        __syncthreads();
        for (int i = tid; i < 1024; i += 256)
            ((float4*)sW)[i] = ((const float4*)(Wn + ((size_t)k * 128 + d0) * 128))[i];
        __syncthreads();
#pragma unroll 2
        for (int dd = 0; dd < 32; dd++) {
            int d = d0 + dd;
            float a0 = sq2[(tq * 4 + 0) * 128 + d];
            float a1 = sq2[(tq * 4 + 1) * 128 + d];
            float a2 = sq2[(tq * 4 + 2) * 128 + d];
            float a3 = sq2[(tq * 4 + 3) * 128 + d];
            float4 bv = *(float4*)(sW + dd * 128 + tn * 4);
            acc[0][0]+=a0*bv.x; acc[0][1]+=a0*bv.y; acc[0][2]+=a0*bv.z; acc[0][3]+=a0*bv.w;
            acc[1][0]+=a1*bv.x; acc[1][1]+=a1*bv.y; acc[1][2]+=a1*bv.z; acc[1][3]+=a1*bv.w;
            acc[2][0]+=a2*bv.x; acc[2][1]+=a2*bv.y; acc[2][2]+=a2*bv.z; acc[2][3]+=a2*bv.w;
            acc[3][0]+=a3*bv.x; acc[3][1]+=a3*bv.y; acc[3][2]+=a3*bv.z; acc[3][3]+=a3*bv.w;
        }
    }
    float* ob = out + ((size_t)b * 16 + k) * 4096;  // [e][q]
#pragma unroll
    for (int j = 0; j < 4; j++) {
        int e = tn * 4 + j;
        *(float4*)(ob + e * 32 + tq * 4) =
            make_float4(acc[0][j], acc[1][j], acc[2][j], acc[3][j]);
    }
}

// ---------------- lq / ld : [nodes,128] @ VnT slice -> [nodes,16] ------------
__global__ __launch_bounds__(256) void lqld_kern(const float* __restrict__ feat,
                                                 const float* __restrict__ Vn, int off,
                                                 float* __restrict__ out) {
    __shared__ float sV[16 * 132];
    __shared__ float sf[64 * 132];
    const int n0 = blockIdx.x * 64;
    const int tid = threadIdx.x;
    for (int i = tid; i < 512; i += 256) {
        int k = i >> 5, d4 = i & 31;
        float4 v = *(const float4*)(Vn + k * 256 + off + d4 * 4);
        float* p = sV + k * 132 + d4 * 4;
        p[0] = v.x; p[1] = v.y; p[2] = v.z; p[3] = v.w;
    }
    for (int i = tid; i < 2048; i += 256) {
        int nn = i >> 5, d4 = i & 31;
        float4 v = *(const float4*)(feat + (size_t)(n0 + nn) * 128 + d4 * 4);
        float* p = sf + nn * 132 + d4 * 4;
        p[0] = v.x; p[1] = v.y; p[2] = v.z; p[3] = v.w;
    }
    __syncthreads();
    int node = tid >> 2, k0 = (tid & 3) * 4;
    float s0 = 0.f, s1 = 0.f, s2 = 0.f, s3 = 0.f;
#pragma unroll 4
    for (int d = 0; d < 128; d++) {
        float f = sf[node * 132 + d];
        s0 += f * sV[(k0 + 0) * 132 + d];
        s1 += f * sV[(k0 + 1) * 132 + d];
        s2 += f * sV[(k0 + 2) * 132 + d];
        s3 += f * sV[(k0 + 3) * 132 + d];
    }
    *(float4*)(out + (size_t)(n0 + node) * 16 + k0) = make_float4(s0, s1, s2, s3);
}

// ----------------------- fused bilinear + sigmoid level ----------------------
#define LV_SMEM ((16384 + 4096 + 512 + 2048 + 32 + 16) * 4)
template<bool HAS_B>
__global__ __launch_bounds__(256, 2) void level_kern(
    const float* __restrict__ qw, const float* __restrict__ dT,
    const float* __restrict__ lq, const float* __restrict__ ld,
    const float* __restrict__ bn, const float* __restrict__ att,
    const float* __restrict__ wk,
    float* __restrict__ outA, float* __restrict__ outB) {
    extern __shared__ float sm[];
    float* sd  = sm;                 // [128e][128n]
    float* sa  = sm + 16384;         // [128e][32q]
    float* slq = sa + 4096;          // [16k][32q]
    float* sld = slq + 512;          // [16k][128n]
    float* swk = sld + 2048;         // [32]
    float* sbn = swk + 32;           // [16]
    const int b = blockIdx.y;
    const int n0 = blockIdx.x * 128;
    const int tid = threadIdx.x;
    const int tq = tid >> 5, tn = tid & 31;

    for (int i = tid; i < 4096; i += 256) {
        int e = i >> 5, c = i & 31;
        ((float4*)sd)[i] = *(const float4*)(dT + ((size_t)b * 128 + e) * 512 + n0 + c * 4);
    }
    for (int i = tid; i < 512; i += 256) {
        int k = i >> 5, q = i & 31;
        slq[i] = lq[((size_t)b * 32 + q) * 16 + k];
    }
    for (int i = tid; i < 2048; i += 256) {
        int k = i >> 7, n = i & 127;
        sld[i] = ld[((size_t)b * 512 + n0 + n) * 16 + k];
    }
    if (tid < 32) swk[tid] = wk[tid];
    if (tid < 16) sbn[tid] = bn[tid];

    float accA[4][4], accB[4][4];
#pragma unroll
    for (int i = 0; i < 4; i++)
#pragma unroll
        for (int j = 0; j < 4; j++) { accA[i][j] = 0.f; accB[i][j] = 0.f; }

    for (int k = 0; k < 16; k++) {
        __syncthreads();
        const float4* src = (const float4*)(qw + (((size_t)b * 16 + k) << 12));
        for (int i = tid; i < 1024; i += 256) ((float4*)sa)[i] = src[i];
        __syncthreads();

        float bil[4][4];
#pragma unroll
        for (int i = 0; i < 4; i++)
#pragma unroll
            for (int j = 0; j < 4; j++) bil[i][j] = 0.f;
#pragma unroll 2
        for (int e = 0; e < 128; e++) {
            float4 av = *(float4*)(sa + e * 32 + tq * 4);
            float4 bv = *(float4*)(sd + e * 128 + tn * 4);
            bil[0][0]+=av.x*bv.x; bil[0][1]+=av.x*bv.y; bil[0][2]+=av.x*bv.z; bil[0][3]+=av.x*bv.w;
            bil[1][0]+=av.y*bv.x; bil[1][1]+=av.y*bv.y; bil[1][2]+=av.y*bv.z; bil[1][3]+=av.y*bv.w;
            bil[2][0]+=av.z*bv.x; bil[2][1]+=av.z*bv.y; bil[2][2]+=av.z*bv.z; bil[2][3]+=av.z*bv.w;
            bil[3][0]+=av.w*bv.x; bil[3][1]+=av.w*bv.y; bil[3][2]+=av.w*bv.z; bil[3][3]+=av.w*bv.w;
        }
        float al = swk[k], be = HAS_B ? swk[16 + k] : 0.f, bk = sbn[k];
#pragma unroll
        for (int i = 0; i < 4; i++) {
            float lqi = slq[k * 32 + tq * 4 + i];
#pragma unroll
            for (int j = 0; j < 4; j++) {
                float x = bil[i][j] + lqi + sld[k * 128 + tn * 4 + j] + bk;
                float sg = 1.f / (1.f + __expf(-x));
                accA[i][j] += al * sg;
                if (HAS_B) accB[i][j] += be * sg;
            }
        }
    }
#pragma unroll
    for (int i = 0; i < 4; i++) {
        size_t o = ((size_t)b * 32 + tq * 4 + i) * 512 + n0 + tn * 4;
        float4 at = *(const float4*)(att + o);
        *(float4*)(outA + o) = make_float4(accA[i][0]*at.x, accA[i][1]*at.y,
                                           accA[i][2]*at.z, accA[i][3]*at.w);
        if (HAS_B) {
            float4 pb = *(float4*)(outB + o);
            pb.x += accB[i][0]*at.x; pb.y += accB[i][1]*at.y;
            pb.z += accB[i][2]*at.z; pb.w += accB[i][3]*at.w;
            *(float4*)(outB + o) = pb;
        }
    }
}

// ----------------------------- softmaxes -------------------------------------
__device__ __forceinline__ float warp_max(float v) {
#pragma unroll
    for (int o = 16; o > 0; o >>= 1) v = fmaxf(v, __shfl_xor_sync(0xffffffffu, v, o));
    return v;
}
__device__ __forceinline__ float warp_sum(float v) {
#pragma unroll
    for (int o = 16; o > 0; o >>= 1) v += __shfl_xor_sync(0xffffffffu, v, o);
    return v;
}

__global__ void row_softmax512(float* __restrict__ p, float scale) {
    int row = blockIdx.x * 8 + (threadIdx.x >> 5);
    int lane = threadIdx.x & 31;
    float* r = p + (size_t)row * 512 + lane * 16;
    float v[16];
#pragma unroll
    for (int j = 0; j < 4; j++) {
        float4 t = *(float4*)(r + j * 4);
        v[j*4+0]=t.x*scale; v[j*4+1]=t.y*scale; v[j*4+2]=t.z*scale; v[j*4+3]=t.w*scale;
    }
    float m = -1e30f;
#pragma unroll
    for (int i = 0; i < 16; i++) m = fmaxf(m, v[i]);
    m = warp_max(m);
    float s = 0.f;
#pragma unroll
    for (int i = 0; i < 16; i++) { v[i] = __expf(v[i] - m); s += v[i]; }
    s = warp_sum(s);
    float inv = 1.f / s;
#pragma unroll
    for (int j = 0; j < 4; j++)
        *(float4*)(r + j * 4) = make_float4(v[j*4+0]*inv, v[j*4+1]*inv, v[j*4+2]*inv, v[j*4+3]*inv);
}

__global__ void final_kern(const float* __restrict__ e1, const float* __restrict__ acc,
                           const float* __restrict__ e3, const float* __restrict__ wk,
                           float* __restrict__ out) {
    float w0 = wk[96], w2 = wk[97];
    int row = blockIdx.x * 8 + (threadIdx.x >> 5);
    int lane = threadIdx.x & 31;
    size_t base = (size_t)row * 512 + lane * 16;
    float v[16];
#pragma unroll
    for (int j = 0; j < 4; j++) {
        float4 a = *(const float4*)(e1 + base + j * 4);
        float4 b = *(const float4*)(acc + base + j * 4);
        float4 c = *(const float4*)(e3 + base + j * 4);
        v[j*4+0] = w0*a.x + b.x + w2*c.x;
        v[j*4+1] = w0*a.y + b.y + w2*c.y;
        v[j*4+2] = w0*a.z + b.z + w2*c.z;
        v[j*4+3] = w0*a.w + b.w + w2*c.w;
    }
    float m = -1e30f;
#pragma unroll
    for (int i = 0; i < 16; i++) m = fmaxf(m, v[i]);
    m = warp_max(m);
    float s = 0.f;
#pragma unroll
    for (int i = 0; i < 16; i++) { v[i] = __expf(v[i] - m); s += v[i]; }
    s = warp_sum(s);
    float inv = 1.f / s;
#pragma unroll
    for (int j = 0; j < 4; j++)
        *(float4*)(out + base + j * 4) =
            make_float4(v[j*4+0]*inv, v[j*4+1]*inv, v[j*4+2]*inv, v[j*4+3]*inv);
}

// -------------------- folded weight preparation ------------------------------
__global__ void prep_wk(const float* __restrict__ cw1, const float* __restrict__ cw2,
                        const float* __restrict__ cw3, const float* __restrict__ w_end,
                        float* __restrict__ wk) {
    int k = threadIdx.x;
    if (k < 16) {
        wk[k]      = cw1[k];                              wk[16 + k] = 0.f;
        wk[32 + k] = w_end[1] * cw2[k] + w_end[19 + k];   wk[48 + k] = 0.f;
        wk[64 + k] = cw3[k];
        wk[80 + k] = w_end[3 + k] + w_end[35 + k];
    }
    if (k == 0) { wk[96] = w_end[0]; wk[97] = w_end[2]; }
}

// ------------------------------- host side -----------------------------------
static inline void* symaddr(const void* sym) {
    void* p = nullptr;
    cudaGetSymbolAddress(&p, sym);
    return p;
}

extern "C" void kernel_launch(void* const* d_in, const int* in_sizes, int n_in,
                              void* d_out, int out_size) {
    // ---- resolve input order (signature order vs dict order) ----
    const float *x_d, *x_q;
    const int *ei_d, *ei_q;
    if (in_sizes[1] == 2 * EDM) {           // x_d, edge_index_d, x_q, edge_index_q
        x_d = (const float*)d_in[0]; ei_d = (const int*)d_in[1];
        x_q = (const float*)d_in[2]; ei_q = (const int*)d_in[3];
    } else {                                 // x_d, x_q, edge_index_d, edge_index_q
        x_d = (const float*)d_in[0]; x_q = (const float*)d_in[1];
        ei_d = (const int*)d_in[2]; ei_q = (const int*)d_in[3];
    }
    const float* W1 = (const float*)d_in[6];  const float* b1 = (const float*)d_in[7];
    const float* W2 = (const float*)d_in[8];  const float* b2 = (const float*)d_in[9];
    const float* W3 = (const float*)d_in[10]; const float* b3 = (const float*)d_in[11];
    const float* Wn[3] = {(const float*)d_in[12], (const float*)d_in[17], (const float*)d_in[22]};
    const float* Vn[3] = {(const float*)d_in[13], (const float*)d_in[18], (const float*)d_in[23]};
    const float* bn[3] = {(const float*)d_in[14], (const float*)d_in[19], (const float*)d_in[24]};
    const float* cw1 = (const float*)d_in[15];
    const float* cw2 = (const float*)d_in[20];
    const float* cw3 = (const float*)d_in[25];
    const float* w_end = (const float*)d_in[27];

    cudaFuncSetAttribute(level_kern<false>, cudaFuncAttributeMaxDynamicSharedMemorySize, LV_SMEM);
    cudaFuncSetAttribute(level_kern<true>,  cudaFuncAttributeMaxDynamicSharedMemorySize, LV_SMEM);
    cudaFuncSetAttribute(s_gemm,            cudaFuncAttributeMaxDynamicSharedMemorySize, SG_SMEM);

    float* p_dinv_d = (float*)symaddr(g_dinv_d); float* p_dinv_q = (float*)symaddr(g_dinv_q);
    int* p_indeg_d = (int*)symaddr(g_indeg_d);   int* p_indeg_q = (int*)symaddr(g_indeg_q);
    int* p_rows_d = (int*)symaddr(g_rows_d);     int* p_rows_q = (int*)symaddr(g_rows_q);
    int* p_fill_d = (int*)symaddr(g_fill_d);     int* p_fill_q = (int*)symaddr(g_fill_q);
    int* p_cols_d = (int*)symaddr(g_cols_d);     int* p_cols_q = (int*)symaddr(g_cols_q);
    float* p_vals_d = (float*)symaddr(g_vals_d); float* p_vals_q = (float*)symaddr(g_vals_q);
    float* p_xw = (float*)symaddr(g_xw);
    float* p_hd = (float*)symaddr(g_hd);         float* p_hq = (float*)symaddr(g_hq);
    float* p_dT = (float*)symaddr(g_dT);         float* p_qw = (float*)symaddr(g_qw);
    float* p_att = (float*)symaddr(g_att);
    float* p_lq = (float*)symaddr(g_lq);         float* p_ld = (float*)symaddr(g_ld);
    float* p_e1 = (float*)symaddr(g_e1);         float* p_e3 = (float*)symaddr(g_e3);
    float* p_acc = (float*)symaddr(g_acc);       float* p_wk = (float*)symaddr(g_wk);
    float* out = (float*)d_out;

    const int* src_d = ei_d;           const int* dst_d = ei_d + EDM;
    const int* src_q = ei_q;           const int* dst_q = ei_q + EQM;

    prep_wk<<<1, 32>>>(cw1, cw2, cw3, w_end, p_wk);

    // ---- CSR build (data + query) ----
    zero2_kern<<<(NDN + 255) / 256, 256>>>(p_indeg_d, p_fill_d, NDN);
    zero2_kern<<<(NQN + 255) / 256, 256>>>(p_indeg_q, p_fill_q, NQN);
    count_deg_kern<<<EDM / 256, 256>>>(dst_d, EDM, p_indeg_d);
    count_deg_kern<<<EQM / 256, 256>>>(dst_q, EQM, p_indeg_q);
    dinv_kern<<<(NDN + 255) / 256, 256>>>(p_indeg_d, p_dinv_d, NDN);
    dinv_kern<<<(NQN + 255) / 256, 256>>>(p_indeg_q, p_dinv_q, NQN);
    scan_csr_kern<<<BBATCH, 512>>>(p_indeg_d, p_rows_d, NDD, NDD * 8);
    scan_csr_kern<<<BBATCH, 32>>>(p_indeg_q, p_rows_q, NQD, NQD * 8);
    fill_csr_kern<<<EDM / 256, 256>>>(src_d, dst_d, EDM, p_dinv_d, p_rows_d, p_fill_d, p_cols_d, p_vals_d);
    fill_csr_kern<<<EQM / 256, 256>>>(src_q, dst_q, EQM, p_dinv_q, p_rows_q, p_fill_q, p_cols_q, p_vals_q);

    // ---- 3-layer GCN, data side ----
    sgemm_xw<<<NDN / 128, 256>>>(x_d, W1, p_xw, DINF);
    spmm_gcn<<<NDN * 32 / 256, 256>>>(p_xw, p_rows_d, p_cols_d, p_vals_d, p_indeg_d, p_dinv_d, b1, p_hd, NDN);
    sgemm_xw<<<NDN / 128, 256>>>(p_hd, W2, p_xw, DDF);
    spmm_gcn<<<NDN * 32 / 256, 256>>>(p_xw, p_rows_d, p_cols_d, p_vals_d, p_indeg_d, p_dinv_d, b2, p_hd + (size_t)NDN * DDF, NDN);
    sgemm_xw<<<NDN / 128, 256>>>(p_hd + (size_t)NDN * DDF, W3, p_xw, DDF);
    spmm_gcn<<<NDN * 32 / 256, 256>>>(p_xw, p_rows_d, p_cols_d, p_vals_d, p_indeg_d, p_dinv_d, b3, p_hd + (size_t)2 * NDN * DDF, NDN);

    // ---- 3-layer GCN, query side ----
    sgemm_xw<<<NQN / 128, 256>>>(x_q, W1, p_xw, DINF);
    spmm_gcn<<<NQN * 32 / 256, 256>>>(p_xw, p_rows_q, p_cols_q, p_vals_q, p_indeg_q, p_dinv_q, b1, p_hq, NQN);
    sgemm_xw<<<NQN / 128, 256>>>(p_hq, W2, p_xw, DDF);
    spmm_gcn<<<NQN * 32 / 256, 256>>>(p_xw, p_rows_q, p_cols_q, p_vals_q, p_indeg_q, p_dinv_q, b2, p_hq + (size_t)NQN * DDF, NQN);
    sgemm_xw<<<NQN / 128, 256>>>(p_hq + (size_t)NQN * DDF, W3, p_xw, DDF);
    spmm_gcn<<<NQN * 32 / 256, 256>>>(p_xw, p_rows_q, p_cols_q, p_vals_q, p_indeg_q, p_dinv_q, b3, p_hq + (size_t)2 * NQN * DDF, NQN);

    // ---- three attention/NTN levels ----
    float* levelA[3] = {p_e1, p_acc, p_e3};
    for (int l = 0; l < 3; l++) {
        const float* qf = p_hq + (size_t)l * NQN * DDF;
        const float* df = p_hd + (size_t)l * NDN * DDF;
        transpose_dk<<<dim3(4, 16, BBATCH), dim3(32, 8)>>>(df, p_dT);
        s_gemm<<<dim3(4, BBATCH), 256, SG_SMEM>>>(qf, p_dT, p_att);
        row_softmax512<<<256, 256>>>(p_att, 0.08838834764831845f);  // 1/sqrt(128)
        qw_gemm<<<dim3(16, BBATCH), 256>>>(qf, Wn[l], p_qw);
        lqld_kern<<<NQN / 64, 256>>>(qf, Vn[l], 0, p_lq);
        lqld_kern<<<NDN / 64, 256>>>(df, Vn[l], DDF, p_ld);
        if (l < 2)
            level_kern<false><<<dim3(4, BBATCH), 256, LV_SMEM>>>(
                p_qw, p_dT, p_lq, p_ld, bn[l], p_att, p_wk + l * 32, levelA[l], nullptr);
        else
            level_kern<true><<<dim3(4, BBATCH), 256, LV_SMEM>>>(
                p_qw, p_dT, p_lq, p_ld, bn[l], p_att, p_wk + l * 32, p_e3, p_acc);
    }

    // ---- softmaxes + final combine ----
    row_softmax512<<<256, 256>>>(p_e1, 1.0f);
    row_softmax512<<<256, 256>>>(p_e3, 1.0f);
    final_kern<<<256, 256>>>(p_e1, p_acc, p_e3, p_wk, out);
}

// round 4
// speedup vs baseline: 1.3083x; 1.3083x over previous
#include <cuda_runtime.h>
#include <cuda_bf16.h>
#include <math.h>
#include <stdint.h>

#define BBATCH 64
#define NQD    32
#define NDD    512
#define DINF   64
#define DDF    128
#define KKN    16
#define NDN    (BBATCH*NDD)      // 32768
#define NQN    (BBATCH*NQD)      // 2048
#define EDM    (NDN*8)           // 262144
#define EQM    (NQN*8)           // 16384

// ------------------------- static device scratch ----------------------------
__device__ float g_dinv_d[NDN];
__device__ float g_dinv_q[NQN];
__device__ int   g_indeg_d[NDN];
__device__ int   g_indeg_q[NQN];
__device__ int   g_rows_d[NDN];
__device__ int   g_rows_q[NQN];
__device__ int   g_fill_d[NDN];
__device__ int   g_fill_q[NQN];
__device__ int   g_cols_d[EDM];
__device__ float g_vals_d[EDM];
__device__ int   g_cols_q[EQM];
__device__ float g_vals_q[EQM];
__device__ float g_xw[NDN*DDF];
__device__ float g_hd[3*NDN*DDF];
__device__ float g_hq[3*NQN*DDF];
__device__ float g_dT[(size_t)BBATCH*DDF*NDD];
__device__ float g_att[(size_t)BBATCH*NQD*NDD];
__device__ float g_lq[NQN*KKN];
__device__ float g_ld[NDN*KKN];
__device__ float g_e1[(size_t)BBATCH*NQD*NDD];
__device__ float g_e3[(size_t)BBATCH*NQD*NDD];
__device__ float g_acc[(size_t)BBATCH*NQD*NDD];
__device__ float g_wk[128];
// split-bf16 operands for HMMA
__device__ __nv_bfloat16 g_qwh[(size_t)BBATCH*512*DDF];  // rows = q*16+k
__device__ __nv_bfloat16 g_qwl[(size_t)BBATCH*512*DDF];
__device__ __nv_bfloat16 g_dh[(size_t)NDN*DDF];
__device__ __nv_bfloat16 g_dl[(size_t)NDN*DDF];

// --------------------------- PTX helpers -------------------------------------
__device__ __forceinline__ uint32_t smem_u32(const void* p) {
    uint32_t a;
    asm("{ .reg .u64 t; cvta.to.shared.u64 t, %1; cvt.u32.u64 %0, t; }" : "=r"(a) : "l"(p));
    return a;
}
#define LDSM_X4(r, a) \
    asm volatile("ldmatrix.sync.aligned.m8n8.x4.shared.b16 {%0,%1,%2,%3}, [%4];" \
        : "=r"((r)[0]), "=r"((r)[1]), "=r"((r)[2]), "=r"((r)[3]) : "r"(a))
#define LDSM_X2(r, a) \
    asm volatile("ldmatrix.sync.aligned.m8n8.x2.shared.b16 {%0,%1}, [%2];" \
        : "=r"((r)[0]), "=r"((r)[1]) : "r"(a))
#define MMA16816(d, a, b) \
    asm volatile("mma.sync.aligned.m16n8k16.row.col.f32.bf16.bf16.f32 " \
        "{%0,%1,%2,%3},{%4,%5,%6,%7},{%8,%9},{%0,%1,%2,%3};" \
        : "+f"((d)[0]), "+f"((d)[1]), "+f"((d)[2]), "+f"((d)[3]) \
        : "r"((a)[0]), "r"((a)[1]), "r"((a)[2]), "r"((a)[3]), "r"((b)[0]), "r"((b)[1]))

// ------------------------------ CSR build -----------------------------------
__global__ void zero2_kern(int* __restrict__ a, int* __restrict__ b, int n) {
    int i = blockIdx.x * blockDim.x + threadIdx.x;
    if (i < n) { a[i] = 0; b[i] = 0; }
}
__global__ void count_deg_kern(const int* __restrict__ dst, int E, int* __restrict__ indeg) {
    int e = blockIdx.x * blockDim.x + threadIdx.x;
    if (e < E) atomicAdd(&indeg[dst[e]], 1);
}
__global__ void dinv_kern(const int* __restrict__ indeg, float* __restrict__ dinv, int n) {
    int i = blockIdx.x * blockDim.x + threadIdx.x;
    if (i < n) dinv[i] = rsqrtf((float)indeg[i] + 1.0f);
}
__global__ void scan_csr_kern(const int* __restrict__ indeg, int* __restrict__ rows,
                              int nper, int eper) {
    __shared__ int s[512];
    int g = blockIdx.x, t = threadIdx.x;
    int v = indeg[g * nper + t];
    s[t] = v; __syncthreads();
    for (int off = 1; off < blockDim.x; off <<= 1) {
        int x = (t >= off) ? s[t - off] : 0;
        __syncthreads();
        s[t] += x;
        __syncthreads();
    }
    rows[g * nper + t] = g * eper + s[t] - v;
}
__global__ void fill_csr_kern(const int* __restrict__ src, const int* __restrict__ dst, int E,
                              const float* __restrict__ dinv, const int* __restrict__ rows,
                              int* __restrict__ fill, int* __restrict__ cols,
                              float* __restrict__ vals) {
    int e = blockIdx.x * blockDim.x + threadIdx.x;
    if (e >= E) return;
    int s = src[e], t = dst[e];
    int p = atomicAdd(&fill[t], 1);
    int idx = rows[t] + p;
    cols[idx] = s;
    vals[idx] = dinv[s] * dinv[t];
}

// -------------------- SGEMM  C[M,128] = A[M,Kd] @ B[Kd,128] -----------------
__global__ __launch_bounds__(256) void sgemm_xw(const float* __restrict__ A,
                                                const float* __restrict__ B,
                                                float* __restrict__ C, int Kd) {
    __shared__ float As[8][128];
    __shared__ float Bs[8][128];
    const int m0 = blockIdx.x * 128;
    const int tid = threadIdx.x;
    const int ar = tid >> 1, ac = (tid & 1) * 4;
    const int br = tid >> 5, bc = (tid & 31) * 4;
    const int ty = tid >> 4, tx = tid & 15;
    float acc[8][8];
#pragma unroll
    for (int i = 0; i < 8; i++)
#pragma unroll
        for (int j = 0; j < 8; j++) acc[i][j] = 0.f;
    for (int k0 = 0; k0 < Kd; k0 += 8) {
        float4 a = *(const float4*)(A + (size_t)(m0 + ar) * Kd + k0 + ac);
        float4 bv = *(const float4*)(B + (size_t)(k0 + br) * 128 + bc);
        __syncthreads();
        As[ac + 0][ar] = a.x; As[ac + 1][ar] = a.y;
        As[ac + 2][ar] = a.z; As[ac + 3][ar] = a.w;
        *(float4*)&Bs[br][bc] = bv;
        __syncthreads();
#pragma unroll
        for (int kk = 0; kk < 8; kk++) {
            float4 a0 = *(float4*)&As[kk][ty * 8];
            float4 a1 = *(float4*)&As[kk][ty * 8 + 4];
            float4 b0 = *(float4*)&Bs[kk][tx * 8];
            float4 b1 = *(float4*)&Bs[kk][tx * 8 + 4];
            float av[8] = {a0.x,a0.y,a0.z,a0.w,a1.x,a1.y,a1.z,a1.w};
            float bw[8] = {b0.x,b0.y,b0.z,b0.w,b1.x,b1.y,b1.z,b1.w};
#pragma unroll
            for (int i = 0; i < 8; i++)
#pragma unroll
                for (int j = 0; j < 8; j++) acc[i][j] += av[i] * bw[j];
        }
    }
#pragma unroll
    for (int i = 0; i < 8; i++) {
        size_t row = (size_t)(m0 + ty * 8 + i) * 128;
        *(float4*)(C + row + tx * 8)     = make_float4(acc[i][0], acc[i][1], acc[i][2], acc[i][3]);
        *(float4*)(C + row + tx * 8 + 4) = make_float4(acc[i][4], acc[i][5], acc[i][6], acc[i][7]);
    }
}

// ------------------- GCN aggregation (warp per node) ------------------------
__global__ void spmm_gcn(const float* __restrict__ h, const int* __restrict__ rows,
                         const int* __restrict__ cols, const float* __restrict__ vals,
                         const int* __restrict__ indeg, const float* __restrict__ dinv,
                         const float* __restrict__ bias, float* __restrict__ out, int N) {
    int t = blockIdx.x * blockDim.x + threadIdx.x;
    int node = t >> 5, lane = t & 31;
    if (node >= N) return;
    float di = dinv[node];
    float self = di * di;
    float4 hv = *(const float4*)(h + (size_t)node * 128 + lane * 4);
    float ax = self * hv.x, ay = self * hv.y, az = self * hv.z, aw = self * hv.w;
    int r0 = rows[node], cnt = indeg[node];
    for (int e = 0; e < cnt; e++) {
        int s = __ldg(&cols[r0 + e]);
        float w = __ldg(&vals[r0 + e]);
        float4 n4 = *(const float4*)(h + (size_t)s * 128 + lane * 4);
        ax += w * n4.x; ay += w * n4.y; az += w * n4.z; aw += w * n4.w;
    }
    float4 b4 = *(const float4*)(bias + lane * 4);
    float4 o;
    o.x = fmaxf(ax + b4.x, 0.f); o.y = fmaxf(ay + b4.y, 0.f);
    o.z = fmaxf(az + b4.z, 0.f); o.w = fmaxf(aw + b4.w, 0.f);
    *(float4*)(out + (size_t)node * 128 + lane * 4) = o;
}

// -------------------------- transpose d -> dT (for att) ----------------------
__global__ void transpose_dk(const float* __restrict__ d, float* __restrict__ dT) {
    __shared__ float ts[32][33];
    int b = blockIdx.z, n0 = blockIdx.y * 32, e0 = blockIdx.x * 32;
    int tx = threadIdx.x, ty = threadIdx.y;
#pragma unroll
    for (int j = 0; j < 32; j += 8)
        ts[ty + j][tx] = d[((size_t)b * 512 + n0 + ty + j) * 128 + e0 + tx];
    __syncthreads();
#pragma unroll
    for (int j = 0; j < 32; j += 8)
        dT[((size_t)b * 128 + e0 + ty + j) * 512 + n0 + tx] = ts[tx][ty + j];
}

// --------------- attention scores S = q @ dT -------------------------------
#define SG_SMEM ((16384 + 128*33) * 4)
__global__ __launch_bounds__(256) void s_gemm(const float* __restrict__ qf,
                                              const float* __restrict__ dT,
                                              float* __restrict__ S) {
    extern __shared__ float sm[];
    float* sd = sm;
    float* sq = sm + 16384;
    const int b = blockIdx.y;
    const int n0 = blockIdx.x * 128;
    const int tid = threadIdx.x;
    const int tq = tid >> 5, tn = tid & 31;
    for (int i = tid; i < 4096; i += 256) {
        int e = i >> 5, c = i & 31;
        ((float4*)sd)[i] = *(const float4*)(dT + ((size_t)b * 128 + e) * 512 + n0 + c * 4);
    }
    for (int i = tid; i < 1024; i += 256) {
        int q = i >> 5, e4 = i & 31;
        float4 v = *(const float4*)(qf + ((size_t)b * 32 + q) * 128 + e4 * 4);
        sq[(e4 * 4 + 0) * 33 + q] = v.x;
        sq[(e4 * 4 + 1) * 33 + q] = v.y;
        sq[(e4 * 4 + 2) * 33 + q] = v.z;
        sq[(e4 * 4 + 3) * 33 + q] = v.w;
    }
    __syncthreads();
    float acc[4][4];
#pragma unroll
    for (int i = 0; i < 4; i++)
#pragma unroll
        for (int j = 0; j < 4; j++) acc[i][j] = 0.f;
#pragma unroll 2
    for (int e = 0; e < 128; e++) {
        float a0 = sq[e * 33 + tq * 4 + 0];
        float a1 = sq[e * 33 + tq * 4 + 1];
        float a2 = sq[e * 33 + tq * 4 + 2];
        float a3 = sq[e * 33 + tq * 4 + 3];
        float4 bv = *(float4*)(sd + e * 128 + tn * 4);
        acc[0][0]+=a0*bv.x; acc[0][1]+=a0*bv.y; acc[0][2]+=a0*bv.z; acc[0][3]+=a0*bv.w;
        acc[1][0]+=a1*bv.x; acc[1][1]+=a1*bv.y; acc[1][2]+=a1*bv.z; acc[1][3]+=a1*bv.w;
        acc[2][0]+=a2*bv.x; acc[2][1]+=a2*bv.y; acc[2][2]+=a2*bv.z; acc[2][3]+=a2*bv.w;
        acc[3][0]+=a3*bv.x; acc[3][1]+=a3*bv.y; acc[3][2]+=a3*bv.z; acc[3][3]+=a3*bv.w;
    }
#pragma unroll
    for (int i = 0; i < 4; i++) {
        size_t o = ((size_t)b * 32 + tq * 4 + i) * 512 + n0 + tn * 4;
        *(float4*)(S + o) = make_float4(acc[i][0], acc[i][1], acc[i][2], acc[i][3]);
    }
}

// ------ qW (split bf16): rows = q*16+k, cols = e -----------------------------
__global__ __launch_bounds__(256) void qw_gemm(const float* __restrict__ qf,
                                               const float* __restrict__ Wn,
                                               __nv_bfloat16* __restrict__ oh,
                                               __nv_bfloat16* __restrict__ ol) {
    __shared__ float sq2[32 * 128];
    __shared__ float sW[32 * 128];
    const int k = blockIdx.x, b = blockIdx.y;
    const int tid = threadIdx.x;
    const int tq = tid >> 5, tn = tid & 31;
    for (int i = tid; i < 1024; i += 256)
        ((float4*)sq2)[i] = ((const float4*)(qf + (size_t)b * 4096))[i];
    float acc[4][4];
#pragma unroll
    for (int i = 0; i < 4; i++)
#pragma unroll
        for (int j = 0; j < 4; j++) acc[i][j] = 0.f;
    for (int d0 = 0; d0 < 128; d0 += 32) {
        __syncthreads();
        for (int i = tid; i < 1024; i += 256)
            ((float4*)sW)[i] = ((const float4*)(Wn + ((size_t)k * 128 + d0) * 128))[i];
        __syncthreads();
#pragma unroll 2
        for (int dd = 0; dd < 32; dd++) {
            int d = d0 + dd;
            float a0 = sq2[(tq * 4 + 0) * 128 + d];
            float a1 = sq2[(tq * 4 + 1) * 128 + d];
            float a2 = sq2[(tq * 4 + 2) * 128 + d];
            float a3 = sq2[(tq * 4 + 3) * 128 + d];
            float4 bv = *(float4*)(sW + dd * 128 + tn * 4);
            acc[0][0]+=a0*bv.x; acc[0][1]+=a0*bv.y; acc[0][2]+=a0*bv.z; acc[0][3]+=a0*bv.w;
            acc[1][0]+=a1*bv.x; acc[1][1]+=a1*bv.y; acc[1][2]+=a1*bv.z; acc[1][3]+=a1*bv.w;
            acc[2][0]+=a2*bv.x; acc[2][1]+=a2*bv.y; acc[2][2]+=a2*bv.z; acc[2][3]+=a2*bv.w;
            acc[3][0]+=a3*bv.x; acc[3][1]+=a3*bv.y; acc[3][2]+=a3*bv.z; acc[3][3]+=a3*bv.w;
        }
    }
#pragma unroll
    for (int i = 0; i < 4; i++) {
        int q = tq * 4 + i;
        size_t row = (size_t)b * 512 + q * 16 + k;
        float h0 = acc[i][0], h1 = acc[i][1], h2 = acc[i][2], h3 = acc[i][3];
        __nv_bfloat162 p0 = __floats2bfloat162_rn(h0, h1);
        __nv_bfloat162 p1 = __floats2bfloat162_rn(h2, h3);
        *(__nv_bfloat162*)(oh + row * 128 + tn * 4)     = p0;
        *(__nv_bfloat162*)(oh + row * 128 + tn * 4 + 2) = p1;
        float l0 = h0 - __bfloat162float(p0.x), l1 = h1 - __bfloat162float(p0.y);
        float l2 = h2 - __bfloat162float(p1.x), l3 = h3 - __bfloat162float(p1.y);
        *(__nv_bfloat162*)(ol + row * 128 + tn * 4)     = __floats2bfloat162_rn(l0, l1);
        *(__nv_bfloat162*)(ol + row * 128 + tn * 4 + 2) = __floats2bfloat162_rn(l2, l3);
    }
}

// ------------------ split f32 -> (hi, lo) bf16, elementwise ------------------
__global__ void split_bf16_kern(const float* __restrict__ x, __nv_bfloat16* __restrict__ hi,
                                __nv_bfloat16* __restrict__ lo, int n2) {
    int i = blockIdx.x * blockDim.x + threadIdx.x;
    if (i >= n2) return;
    float2 v = ((const float2*)x)[i];
    __nv_bfloat162 h = __floats2bfloat162_rn(v.x, v.y);
    ((__nv_bfloat162*)hi)[i] = h;
    ((__nv_bfloat162*)lo)[i] = __floats2bfloat162_rn(v.x - __bfloat162float(h.x),
                                                     v.y - __bfloat162float(h.y));
}

// ---------------- lq / ld : [nodes,128] @ VnT slice -> [nodes,16] ------------
__global__ __launch_bounds__(256) void lqld_kern(const float* __restrict__ feat,
                                                 const float* __restrict__ Vn, int off,
                                                 float* __restrict__ out) {
    __shared__ float sV[16 * 132];
    __shared__ float sf[64 * 132];
    const int n0 = blockIdx.x * 64;
    const int tid = threadIdx.x;
    for (int i = tid; i < 512; i += 256) {
        int k = i >> 5, d4 = i & 31;
        float4 v = *(const float4*)(Vn + k * 256 + off + d4 * 4);
        float* p = sV + k * 132 + d4 * 4;
        p[0] = v.x; p[1] = v.y; p[2] = v.z; p[3] = v.w;
    }
    for (int i = tid; i < 2048; i += 256) {
        int nn = i >> 5, d4 = i & 31;
        float4 v = *(const float4*)(feat + (size_t)(n0 + nn) * 128 + d4 * 4);
        float* p = sf + nn * 132 + d4 * 4;
        p[0] = v.x; p[1] = v.y; p[2] = v.z; p[3] = v.w;
    }
    __syncthreads();
    int node = tid >> 2, k0 = (tid & 3) * 4;
    float s0 = 0.f, s1 = 0.f, s2 = 0.f, s3 = 0.f;
#pragma unroll 4
    for (int d = 0; d < 128; d++) {
        float f = sf[node * 132 + d];
        s0 += f * sV[(k0 + 0) * 132 + d];
        s1 += f * sV[(k0 + 1) * 132 + d];
        s2 += f * sV[(k0 + 2) * 132 + d];
        s3 += f * sV[(k0 + 3) * 132 + d];
    }
    *(float4*)(out + (size_t)(n0 + node) * 16 + k0) = make_float4(s0, s1, s2, s3);
}

// ============ HMMA fused NTN level (split-bf16 mma.sync m16n8k16) ============
// A[m=q*16+k, e] (rows mt*128..), B[n, e] (rows nt*64..), contraction over e=128.
// Each warp owns one q (16 k-rows) x 64 n. Epilogue: sigmoid + k-reduce + att.
#define OFF_AH 0
#define OFF_AL 34816
#define OFF_BH 69632
#define OFF_BL 87040
#define OFF_LD 104448
#define OFF_LQ 108544
#define OFF_WK 109056
#define OFF_BN 109184
#define NTN_SMEM 109248

template<int HAS_B>
__global__ __launch_bounds__(256, 2) void ntn_hmma_kern(
    const __nv_bfloat16* __restrict__ Ah, const __nv_bfloat16* __restrict__ Al,
    const __nv_bfloat16* __restrict__ Bh, const __nv_bfloat16* __restrict__ Bl,
    const float* __restrict__ lq, const float* __restrict__ ld,
    const float* __restrict__ bn, const float* __restrict__ att,
    const float* __restrict__ wk,
    float* __restrict__ outA, float* __restrict__ outB) {
    extern __shared__ char smem[];
    const int tid = threadIdx.x;
    const int warp = tid >> 5, lane = tid & 31;
    const int b = blockIdx.z, mt = blockIdx.y, nt = blockIdx.x;

    __nv_bfloat16* sAh = (__nv_bfloat16*)(smem + OFF_AH);
    __nv_bfloat16* sAl = (__nv_bfloat16*)(smem + OFF_AL);
    __nv_bfloat16* sBh = (__nv_bfloat16*)(smem + OFF_BH);
    __nv_bfloat16* sBl = (__nv_bfloat16*)(smem + OFF_BL);
    float* s_ld = (float*)(smem + OFF_LD);
    float* s_lq = (float*)(smem + OFF_LQ);
    float* s_wk = (float*)(smem + OFF_WK);
    float* s_bn = (float*)(smem + OFF_BN);

    // ---- stage tiles: A 128x128, B 64x128 bf16, rows padded to 136 ----
    for (int i = tid; i < 2048; i += 256) {
        int row = i >> 4, c8 = (i & 15) << 3;
        size_t g = ((size_t)b * 512 + (size_t)mt * 128 + row) * 128 + c8;
        *(uint4*)(sAh + row * 136 + c8) = *(const uint4*)(Ah + g);
        *(uint4*)(sAl + row * 136 + c8) = *(const uint4*)(Al + g);
    }
    for (int i = tid; i < 1024; i += 256) {
        int row = i >> 4, c8 = (i & 15) << 3;
        size_t g = ((size_t)b * 512 + (size_t)nt * 64 + row) * 128 + c8;
        *(uint4*)(sBh + row * 136 + c8) = *(const uint4*)(Bh + g);
        *(uint4*)(sBl + row * 136 + c8) = *(const uint4*)(Bl + g);
    }
    for (int i = tid; i < 256; i += 256)
        ((float4*)s_ld)[i] = ((const float4*)(ld + ((size_t)b * 512 + (size_t)nt * 64) * 16))[i];
    if (tid < 128) s_lq[tid] = lq[((size_t)b * 32 + mt * 8) * 16 + tid];
    if (tid < 32) s_wk[tid] = wk[tid];
    if (tid < 16) s_bn[tid] = bn[tid];
    __syncthreads();

    // ---- ldmatrix base addresses (padded row = 272 bytes) ----
    const int m0 = warp * 16;
    uint32_t sa_h = smem_u32(sAh) + ((m0 + (lane & 15)) * 136 + ((lane & 16) ? 8 : 0)) * 2;
    uint32_t sa_l = sa_h + (OFF_BH - OFF_AL);  // same layout, +34816 bytes
    uint32_t sb_h = smem_u32(sBh) + ((lane & 7) * 136 + ((lane & 8) ? 8 : 0)) * 2;
    uint32_t sb_l = sb_h + (OFF_LD - OFF_BL);  // +17408 bytes

    float acc[8][4];
#pragma unroll
    for (int c = 0; c < 8; c++)
#pragma unroll
        for (int j = 0; j < 4; j++) acc[c][j] = 0.f;

#pragma unroll
    for (int s = 0; s < 8; s++) {
        uint32_t RAh[4], RAl[4];
        LDSM_X4(RAh, sa_h + s * 32);
        LDSM_X4(RAl, sa_l + s * 32);
#pragma unroll
        for (int ch = 0; ch < 8; ch++) {
            uint32_t RBh[2], RBl[2];
            LDSM_X2(RBh, sb_h + ch * 2176 + s * 32);
            LDSM_X2(RBl, sb_l + ch * 2176 + s * 32);
            MMA16816(acc[ch], RAh, RBh);
            MMA16816(acc[ch], RAh, RBl);
            MMA16816(acc[ch], RAl, RBh);
        }
    }

    // ---- epilogue: x = bil + lq[q,k] + ld[n,k] + bn[k]; sum_k w_k*sig(x) ----
    const int q = mt * 8 + warp;
    const int k0 = lane >> 2;            // rows k0 and k0+8
    const int c2 = (lane & 3) * 2;       // cols within n8 chunk
    const float lq0 = s_lq[warp * 16 + k0] + s_bn[k0];
    const float lq1 = s_lq[warp * 16 + k0 + 8] + s_bn[k0 + 8];
    const float al0 = s_wk[k0], al1 = s_wk[k0 + 8];
    const float be0 = HAS_B ? s_wk[16 + k0] : 0.f;
    const float be1 = HAS_B ? s_wk[16 + k0 + 8] : 0.f;

#pragma unroll
    for (int ch = 0; ch < 8; ch++) {
        int n0 = ch * 8 + c2;
        float sg00 = 1.f / (1.f + __expf(-(acc[ch][0] + lq0 + s_ld[n0 * 16 + k0])));
        float sg01 = 1.f / (1.f + __expf(-(acc[ch][1] + lq0 + s_ld[(n0 + 1) * 16 + k0])));
        float sg10 = 1.f / (1.f + __expf(-(acc[ch][2] + lq1 + s_ld[n0 * 16 + k0 + 8])));
        float sg11 = 1.f / (1.f + __expf(-(acc[ch][3] + lq1 + s_ld[(n0 + 1) * 16 + k0 + 8])));
        float u0 = al0 * sg00 + al1 * sg10;
        float u1 = al0 * sg01 + al1 * sg11;
        float v0 = 0.f, v1 = 0.f;
        if (HAS_B) { v0 = be0 * sg00 + be1 * sg10; v1 = be0 * sg01 + be1 * sg11; }
#pragma unroll
        for (int off = 4; off < 32; off <<= 1) {
            u0 += __shfl_xor_sync(0xffffffffu, u0, off);
            u1 += __shfl_xor_sync(0xffffffffu, u1, off);
            if (HAS_B) {
                v0 += __shfl_xor_sync(0xffffffffu, v0, off);
                v1 += __shfl_xor_sync(0xffffffffu, v1, off);
            }
        }
        if (lane < 4) {
            size_t o = ((size_t)b * 32 + q) * 512 + (size_t)nt * 64 + ch * 8 + lane * 2;
            float a0 = att[o], a1 = att[o + 1];
            outA[o]     = u0 * a0;
            outA[o + 1] = u1 * a1;
            if (HAS_B) {
                outB[o]     += v0 * a0;
                outB[o + 1] += v1 * a1;
            }
        }
    }
}

// ----------------------------- softmaxes -------------------------------------
__device__ __forceinline__ float warp_max(float v) {
#pragma unroll
    for (int o = 16; o > 0; o >>= 1) v = fmaxf(v, __shfl_xor_sync(0xffffffffu, v, o));
    return v;
}
__device__ __forceinline__ float warp_sum(float v) {
#pragma unroll
    for (int o = 16; o > 0; o >>= 1) v += __shfl_xor_sync(0xffffffffu, v, o);
    return v;
}

__global__ void row_softmax512(float* __restrict__ p, float scale) {
    int row = blockIdx.x * 8 + (threadIdx.x >> 5);
    int lane = threadIdx.x & 31;
    float* r = p + (size_t)row * 512 + lane * 16;
    float v[16];
#pragma unroll
    for (int j = 0; j < 4; j++) {
        float4 t = *(float4*)(r + j * 4);
        v[j*4+0]=t.x*scale; v[j*4+1]=t.y*scale; v[j*4+2]=t.z*scale; v[j*4+3]=t.w*scale;
    }
    float m = -1e30f;
#pragma unroll
    for (int i = 0; i < 16; i++) m = fmaxf(m, v[i]);
    m = warp_max(m);
    float s = 0.f;
#pragma unroll
    for (int i = 0; i < 16; i++) { v[i] = __expf(v[i] - m); s += v[i]; }
    s = warp_sum(s);
    float inv = 1.f / s;
#pragma unroll
    for (int j = 0; j < 4; j++)
        *(float4*)(r + j * 4) = make_float4(v[j*4+0]*inv, v[j*4+1]*inv, v[j*4+2]*inv, v[j*4+3]*inv);
}

__global__ void final_kern(const float* __restrict__ e1, const float* __restrict__ acc,
                           const float* __restrict__ e3, const float* __restrict__ wk,
                           float* __restrict__ out) {
    float w0 = wk[96], w2 = wk[97];
    int row = blockIdx.x * 8 + (threadIdx.x >> 5);
    int lane = threadIdx.x & 31;
    size_t base = (size_t)row * 512 + lane * 16;
    float v[16];
#pragma unroll
    for (int j = 0; j < 4; j++) {
        float4 a = *(const float4*)(e1 + base + j * 4);
        float4 b = *(const float4*)(acc + base + j * 4);
        float4 c = *(const float4*)(e3 + base + j * 4);
        v[j*4+0] = w0*a.x + b.x + w2*c.x;
        v[j*4+1] = w0*a.y + b.y + w2*c.y;
        v[j*4+2] = w0*a.z + b.z + w2*c.z;
        v[j*4+3] = w0*a.w + b.w + w2*c.w;
    }
    float m = -1e30f;
#pragma unroll
    for (int i = 0; i < 16; i++) m = fmaxf(m, v[i]);
    m = warp_max(m);
    float s = 0.f;
#pragma unroll
    for (int i = 0; i < 16; i++) { v[i] = __expf(v[i] - m); s += v[i]; }
    s = warp_sum(s);
    float inv = 1.f / s;
#pragma unroll
    for (int j = 0; j < 4; j++)
        *(float4*)(out + base + j * 4) =
            make_float4(v[j*4+0]*inv, v[j*4+1]*inv, v[j*4+2]*inv, v[j*4+3]*inv);
}

// -------------------- folded weight preparation ------------------------------
__global__ void prep_wk(const float* __restrict__ cw1, const float* __restrict__ cw2,
                        const float* __restrict__ cw3, const float* __restrict__ w_end,
                        float* __restrict__ wk) {
    int k = threadIdx.x;
    if (k < 16) {
        wk[k]      = cw1[k];                              wk[16 + k] = 0.f;
        wk[32 + k] = w_end[1] * cw2[k] + w_end[19 + k];   wk[48 + k] = 0.f;
        wk[64 + k] = cw3[k];
        wk[80 + k] = w_end[3 + k] + w_end[35 + k];
    }
    if (k == 0) { wk[96] = w_end[0]; wk[97] = w_end[2]; }
}

// ------------------------------- host side -----------------------------------
static inline void* symaddr(const void* sym) {
    void* p = nullptr;
    cudaGetSymbolAddress(&p, sym);
    return p;
}

extern "C" void kernel_launch(void* const* d_in, const int* in_sizes, int n_in,
                              void* d_out, int out_size) {
    const float *x_d, *x_q;
    const int *ei_d, *ei_q;
    if (in_sizes[1] == 2 * EDM) {
        x_d = (const float*)d_in[0]; ei_d = (const int*)d_in[1];
        x_q = (const float*)d_in[2]; ei_q = (const int*)d_in[3];
    } else {
        x_d = (const float*)d_in[0]; x_q = (const float*)d_in[1];
        ei_d = (const int*)d_in[2]; ei_q = (const int*)d_in[3];
    }
    const float* W1 = (const float*)d_in[6];  const float* b1 = (const float*)d_in[7];
    const float* W2 = (const float*)d_in[8];  const float* b2 = (const float*)d_in[9];
    const float* W3 = (const float*)d_in[10]; const float* b3 = (const float*)d_in[11];
    const float* Wn[3] = {(const float*)d_in[12], (const float*)d_in[17], (const float*)d_in[22]};
    const float* Vn[3] = {(const float*)d_in[13], (const float*)d_in[18], (const float*)d_in[23]};
    const float* bn[3] = {(const float*)d_in[14], (const float*)d_in[19], (const float*)d_in[24]};
    const float* cw1 = (const float*)d_in[15];
    const float* cw2 = (const float*)d_in[20];
    const float* cw3 = (const float*)d_in[25];
    const float* w_end = (const float*)d_in[27];

    cudaFuncSetAttribute(s_gemm, cudaFuncAttributeMaxDynamicSharedMemorySize, SG_SMEM);
    cudaFuncSetAttribute(ntn_hmma_kern<0>, cudaFuncAttributeMaxDynamicSharedMemorySize, NTN_SMEM);
    cudaFuncSetAttribute(ntn_hmma_kern<1>, cudaFuncAttributeMaxDynamicSharedMemorySize, NTN_SMEM);

    float* p_dinv_d = (float*)symaddr(g_dinv_d); float* p_dinv_q = (float*)symaddr(g_dinv_q);
    int* p_indeg_d = (int*)symaddr(g_indeg_d);   int* p_indeg_q = (int*)symaddr(g_indeg_q);
    int* p_rows_d = (int*)symaddr(g_rows_d);     int* p_rows_q = (int*)symaddr(g_rows_q);
    int* p_fill_d = (int*)symaddr(g_fill_d);     int* p_fill_q = (int*)symaddr(g_fill_q);
    int* p_cols_d = (int*)symaddr(g_cols_d);     int* p_cols_q = (int*)symaddr(g_cols_q);
    float* p_vals_d = (float*)symaddr(g_vals_d); float* p_vals_q = (float*)symaddr(g_vals_q);
    float* p_xw = (float*)symaddr(g_xw);
    float* p_hd = (float*)symaddr(g_hd);         float* p_hq = (float*)symaddr(g_hq);
    float* p_dT = (float*)symaddr(g_dT);
    float* p_att = (float*)symaddr(g_att);
    float* p_lq = (float*)symaddr(g_lq);         float* p_ld = (float*)symaddr(g_ld);
    float* p_e1 = (float*)symaddr(g_e1);         float* p_e3 = (float*)symaddr(g_e3);
    float* p_acc = (float*)symaddr(g_acc);       float* p_wk = (float*)symaddr(g_wk);
    __nv_bfloat16* p_qwh = (__nv_bfloat16*)symaddr(g_qwh);
    __nv_bfloat16* p_qwl = (__nv_bfloat16*)symaddr(g_qwl);
    __nv_bfloat16* p_dh  = (__nv_bfloat16*)symaddr(g_dh);
    __nv_bfloat16* p_dl  = (__nv_bfloat16*)symaddr(g_dl);
    float* out = (float*)d_out;

    const int* src_d = ei_d;           const int* dst_d = ei_d + EDM;
    const int* src_q = ei_q;           const int* dst_q = ei_q + EQM;

    prep_wk<<<1, 32>>>(cw1, cw2, cw3, w_end, p_wk);

    // ---- CSR build ----
    zero2_kern<<<(NDN + 255) / 256, 256>>>(p_indeg_d, p_fill_d, NDN);
    zero2_kern<<<(NQN + 255) / 256, 256>>>(p_indeg_q, p_fill_q, NQN);
    count_deg_kern<<<EDM / 256, 256>>>(dst_d, EDM, p_indeg_d);
    count_deg_kern<<<EQM / 256, 256>>>(dst_q, EQM, p_indeg_q);
    dinv_kern<<<(NDN + 255) / 256, 256>>>(p_indeg_d, p_dinv_d, NDN);
    dinv_kern<<<(NQN + 255) / 256, 256>>>(p_indeg_q, p_dinv_q, NQN);
    scan_csr_kern<<<BBATCH, 512>>>(p_indeg_d, p_rows_d, NDD, NDD * 8);
    scan_csr_kern<<<BBATCH, 32>>>(p_indeg_q, p_rows_q, NQD, NQD * 8);
    fill_csr_kern<<<EDM / 256, 256>>>(src_d, dst_d, EDM, p_dinv_d, p_rows_d, p_fill_d, p_cols_d, p_vals_d);
    fill_csr_kern<<<EQM / 256, 256>>>(src_q, dst_q, EQM, p_dinv_q, p_rows_q, p_fill_q, p_cols_q, p_vals_q);

    // ---- 3-layer GCN, data ----
    sgemm_xw<<<NDN / 128, 256>>>(x_d, W1, p_xw, DINF);
    spmm_gcn<<<NDN * 32 / 256, 256>>>(p_xw, p_rows_d, p_cols_d, p_vals_d, p_indeg_d, p_dinv_d, b1, p_hd, NDN);
    sgemm_xw<<<NDN / 128, 256>>>(p_hd, W2, p_xw, DDF);
    spmm_gcn<<<NDN * 32 / 256, 256>>>(p_xw, p_rows_d, p_cols_d, p_vals_d, p_indeg_d, p_dinv_d, b2, p_hd + (size_t)NDN * DDF, NDN);
    sgemm_xw<<<NDN / 128, 256>>>(p_hd + (size_t)NDN * DDF, W3, p_xw, DDF);
    spmm_gcn<<<NDN * 32 / 256, 256>>>(p_xw, p_rows_d, p_cols_d, p_vals_d, p_indeg_d, p_dinv_d, b3, p_hd + (size_t)2 * NDN * DDF, NDN);

    // ---- 3-layer GCN, query ----
    sgemm_xw<<<NQN / 128, 256>>>(x_q, W1, p_xw, DINF);
    spmm_gcn<<<NQN * 32 / 256, 256>>>(p_xw, p_rows_q, p_cols_q, p_vals_q, p_indeg_q, p_dinv_q, b1, p_hq, NQN);
    sgemm_xw<<<NQN / 128, 256>>>(p_hq, W2, p_xw, DDF);
    spmm_gcn<<<NQN * 32 / 256, 256>>>(p_xw, p_rows_q, p_cols_q, p_vals_q, p_indeg_q, p_dinv_q, b2, p_hq + (size_t)NQN * DDF, NQN);
    sgemm_xw<<<NQN / 128, 256>>>(p_hq + (size_t)NQN * DDF, W3, p_xw, DDF);
    spmm_gcn<<<NQN * 32 / 256, 256>>>(p_xw, p_rows_q, p_cols_q, p_vals_q, p_indeg_q, p_dinv_q, b3, p_hq + (size_t)2 * NQN * DDF, NQN);

    // ---- three attention/NTN levels ----
    for (int l = 0; l < 3; l++) {
        const float* qf = p_hq + (size_t)l * NQN * DDF;
        const float* df = p_hd + (size_t)l * NDN * DDF;
        transpose_dk<<<dim3(4, 16, BBATCH), dim3(32, 8)>>>(df, p_dT);
        s_gemm<<<dim3(4, BBATCH), 256, SG_SMEM>>>(qf, p_dT, p_att);
        row_softmax512<<<256, 256>>>(p_att, 0.08838834764831845f);
        qw_gemm<<<dim3(16, BBATCH), 256>>>(qf, Wn[l], p_qwh, p_qwl);
        split_bf16_kern<<<(NDN * DDF / 2 + 255) / 256, 256>>>(df, p_dh, p_dl, NDN * DDF / 2);
        lqld_kern<<<NQN / 64, 256>>>(qf, Vn[l], 0, p_lq);
        lqld_kern<<<NDN / 64, 256>>>(df, Vn[l], DDF, p_ld);
        if (l == 0)
            ntn_hmma_kern<0><<<dim3(8, 4, BBATCH), 256, NTN_SMEM>>>(
                p_qwh, p_qwl, p_dh, p_dl, p_lq, p_ld, bn[l], p_att, p_wk, p_e1, nullptr);
        else if (l == 1)
            ntn_hmma_kern<0><<<dim3(8, 4, BBATCH), 256, NTN_SMEM>>>(
                p_qwh, p_qwl, p_dh, p_dl, p_lq, p_ld, bn[l], p_att, p_wk + 32, p_acc, nullptr);
        else
            ntn_hmma_kern<1><<<dim3(8, 4, BBATCH), 256, NTN_SMEM>>>(
                p_qwh, p_qwl, p_dh, p_dl, p_lq, p_ld, bn[l], p_att, p_wk + 64, p_e3, p_acc);
    }

    // ---- softmaxes + final combine ----
    row_softmax512<<<256, 256>>>(p_e1, 1.0f);
    row_softmax512<<<256, 256>>>(p_e3, 1.0f);
    final_kern<<<256, 256>>>(p_e1, p_acc, p_e3, p_wk, out);
}

// round 5
// speedup vs baseline: 1.5832x; 1.2101x over previous
#include <cuda_runtime.h>
#include <cuda_bf16.h>
#include <math.h>
#include <stdint.h>

#define BBATCH 64
#define NQD    32
#define NDD    512
#define DINF   64
#define DDF    128
#define KKN    16
#define NDN    (BBATCH*NDD)      // 32768
#define NQN    (BBATCH*NQD)      // 2048
#define EDM    (NDN*8)           // 262144
#define EQM    (NQN*8)           // 16384

// ------------------------- static device scratch ----------------------------
__device__ float g_dinv_d[NDN];
__device__ float g_dinv_q[NQN];
__device__ int   g_indeg_d[NDN];
__device__ int   g_indeg_q[NQN];
__device__ int   g_rows_d[NDN];
__device__ int   g_rows_q[NQN];
__device__ int   g_fill_d[NDN];
__device__ int   g_fill_q[NQN];
__device__ int   g_cols_d[EDM];
__device__ float g_vals_d[EDM];
__device__ int   g_cols_q[EQM];
__device__ float g_vals_q[EQM];
__device__ float g_xw[NDN*DDF];
__device__ float g_hd[3*NDN*DDF];
__device__ float g_hq[3*NQN*DDF];
__device__ float g_att[(size_t)BBATCH*NQD*NDD];
__device__ float g_lq[NQN*KKN];
__device__ float g_ld[NDN*KKN];
__device__ float g_e1[(size_t)BBATCH*NQD*NDD];
__device__ float g_e3[(size_t)BBATCH*NQD*NDD];
__device__ float g_acc[(size_t)BBATCH*NQD*NDD];
__device__ float g_wk[128];
// split-bf16 operands
__device__ __nv_bfloat16 g_hdh[(size_t)3*NDN*DDF];
__device__ __nv_bfloat16 g_hdl[(size_t)3*NDN*DDF];
__device__ __nv_bfloat16 g_hqh[(size_t)3*NQN*DDF];
__device__ __nv_bfloat16 g_hql[(size_t)3*NQN*DDF];
__device__ __nv_bfloat16 g_qwh[(size_t)BBATCH*512*DDF];  // rows = b*512 + q*16+k
__device__ __nv_bfloat16 g_qwl[(size_t)BBATCH*512*DDF];
__device__ __nv_bfloat16 g_w2th[DDF*DDF], g_w2tl[DDF*DDF];
__device__ __nv_bfloat16 g_w3th[DDF*DDF], g_w3tl[DDF*DDF];
__device__ __nv_bfloat16 g_wnth[(size_t)3*KKN*DDF*DDF], g_wntl[(size_t)3*KKN*DDF*DDF];

// --------------------------- PTX helpers -------------------------------------
__device__ __forceinline__ uint32_t smem_u32(const void* p) {
    uint32_t a;
    asm("{ .reg .u64 t; cvta.to.shared.u64 t, %1; cvt.u32.u64 %0, t; }" : "=r"(a) : "l"(p));
    return a;
}
#define LDSM_X4(r, a) \
    asm volatile("ldmatrix.sync.aligned.m8n8.x4.shared.b16 {%0,%1,%2,%3}, [%4];" \
        : "=r"((r)[0]), "=r"((r)[1]), "=r"((r)[2]), "=r"((r)[3]) : "r"(a))
#define LDSM_X2(r, a) \
    asm volatile("ldmatrix.sync.aligned.m8n8.x2.shared.b16 {%0,%1}, [%2];" \
        : "=r"((r)[0]), "=r"((r)[1]) : "r"(a))
#define MMA16816(d, a, b) \
    asm volatile("mma.sync.aligned.m16n8k16.row.col.f32.bf16.bf16.f32 " \
        "{%0,%1,%2,%3},{%4,%5,%6,%7},{%8,%9},{%0,%1,%2,%3};" \
        : "+f"((d)[0]), "+f"((d)[1]), "+f"((d)[2]), "+f"((d)[3]) \
        : "r"((a)[0]), "r"((a)[1]), "r"((a)[2]), "r"((a)[3]), "r"((b)[0]), "r"((b)[1]))

// ------------------------------ CSR build -----------------------------------
__global__ void zero2_kern(int* __restrict__ a, int* __restrict__ b, int n) {
    int i = blockIdx.x * blockDim.x + threadIdx.x;
    if (i < n) { a[i] = 0; b[i] = 0; }
}
__global__ void count_deg_kern(const int* __restrict__ dst, int E, int* __restrict__ indeg) {
    int e = blockIdx.x * blockDim.x + threadIdx.x;
    if (e < E) atomicAdd(&indeg[dst[e]], 1);
}
__global__ void dinv_kern(const int* __restrict__ indeg, float* __restrict__ dinv, int n) {
    int i = blockIdx.x * blockDim.x + threadIdx.x;
    if (i < n) dinv[i] = rsqrtf((float)indeg[i] + 1.0f);
}
__global__ void scan_csr_kern(const int* __restrict__ indeg, int* __restrict__ rows,
                              int nper, int eper) {
    __shared__ int s[512];
    int g = blockIdx.x, t = threadIdx.x;
    int v = indeg[g * nper + t];
    s[t] = v; __syncthreads();
    for (int off = 1; off < blockDim.x; off <<= 1) {
        int x = (t >= off) ? s[t - off] : 0;
        __syncthreads();
        s[t] += x;
        __syncthreads();
    }
    rows[g * nper + t] = g * eper + s[t] - v;
}
__global__ void fill_csr_kern(const int* __restrict__ src, const int* __restrict__ dst, int E,
                              const float* __restrict__ dinv, const int* __restrict__ rows,
                              int* __restrict__ fill, int* __restrict__ cols,
                              float* __restrict__ vals) {
    int e = blockIdx.x * blockDim.x + threadIdx.x;
    if (e >= E) return;
    int s = src[e], t = dst[e];
    int p = atomicAdd(&fill[t], 1);
    int idx = rows[t] + p;
    cols[idx] = s;
    vals[idx] = dinv[s] * dinv[t];
}

// -------------------- SGEMM layer1  C[M,128] = A[M,64] @ B[64,128] -----------
__global__ __launch_bounds__(256) void sgemm_xw(const float* __restrict__ A,
                                                const float* __restrict__ B,
                                                float* __restrict__ C, int Kd) {
    __shared__ float As[8][128];
    __shared__ float Bs[8][128];
    const int m0 = blockIdx.x * 128;
    const int tid = threadIdx.x;
    const int ar = tid >> 1, ac = (tid & 1) * 4;
    const int br = tid >> 5, bc = (tid & 31) * 4;
    const int ty = tid >> 4, tx = tid & 15;
    float acc[8][8];
#pragma unroll
    for (int i = 0; i < 8; i++)
#pragma unroll
        for (int j = 0; j < 8; j++) acc[i][j] = 0.f;
    for (int k0 = 0; k0 < Kd; k0 += 8) {
        float4 a = *(const float4*)(A + (size_t)(m0 + ar) * Kd + k0 + ac);
        float4 bv = *(const float4*)(B + (size_t)(k0 + br) * 128 + bc);
        __syncthreads();
        As[ac + 0][ar] = a.x; As[ac + 1][ar] = a.y;
        As[ac + 2][ar] = a.z; As[ac + 3][ar] = a.w;
        *(float4*)&Bs[br][bc] = bv;
        __syncthreads();
#pragma unroll
        for (int kk = 0; kk < 8; kk++) {
            float4 a0 = *(float4*)&As[kk][ty * 8];
            float4 a1 = *(float4*)&As[kk][ty * 8 + 4];
            float4 b0 = *(float4*)&Bs[kk][tx * 8];
            float4 b1 = *(float4*)&Bs[kk][tx * 8 + 4];
            float av[8] = {a0.x,a0.y,a0.z,a0.w,a1.x,a1.y,a1.z,a1.w};
            float bw[8] = {b0.x,b0.y,b0.z,b0.w,b1.x,b1.y,b1.z,b1.w};
#pragma unroll
            for (int i = 0; i < 8; i++)
#pragma unroll
                for (int j = 0; j < 8; j++) acc[i][j] += av[i] * bw[j];
        }
    }
#pragma unroll
    for (int i = 0; i < 8; i++) {
        size_t row = (size_t)(m0 + ty * 8 + i) * 128;
        *(float4*)(C + row + tx * 8)     = make_float4(acc[i][0], acc[i][1], acc[i][2], acc[i][3]);
        *(float4*)(C + row + tx * 8 + 4) = make_float4(acc[i][4], acc[i][5], acc[i][6], acc[i][7]);
    }
}

// ------------- GCN aggregation (warp per node), dual emit f32 + split bf16 ---
__global__ void spmm_gcn(const float* __restrict__ h, const int* __restrict__ rows,
                         const int* __restrict__ cols, const float* __restrict__ vals,
                         const int* __restrict__ indeg, const float* __restrict__ dinv,
                         const float* __restrict__ bias, float* __restrict__ out,
                         __nv_bfloat16* __restrict__ oh, __nv_bfloat16* __restrict__ ol,
                         int N) {
    int t = blockIdx.x * blockDim.x + threadIdx.x;
    int node = t >> 5, lane = t & 31;
    if (node >= N) return;
    float di = dinv[node];
    float self = di * di;
    float4 hv = *(const float4*)(h + (size_t)node * 128 + lane * 4);
    float ax = self * hv.x, ay = self * hv.y, az = self * hv.z, aw = self * hv.w;
    int r0 = rows[node], cnt = indeg[node];
    for (int e = 0; e < cnt; e++) {
        int s = __ldg(&cols[r0 + e]);
        float w = __ldg(&vals[r0 + e]);
        float4 n4 = *(const float4*)(h + (size_t)s * 128 + lane * 4);
        ax += w * n4.x; ay += w * n4.y; az += w * n4.z; aw += w * n4.w;
    }
    float4 b4 = *(const float4*)(bias + lane * 4);
    float4 o;
    o.x = fmaxf(ax + b4.x, 0.f); o.y = fmaxf(ay + b4.y, 0.f);
    o.z = fmaxf(az + b4.z, 0.f); o.w = fmaxf(aw + b4.w, 0.f);
    *(float4*)(out + (size_t)node * 128 + lane * 4) = o;
    __nv_bfloat162 h01 = __floats2bfloat162_rn(o.x, o.y);
    __nv_bfloat162 h23 = __floats2bfloat162_rn(o.z, o.w);
    *(__nv_bfloat162*)(oh + (size_t)node * 128 + lane * 4)     = h01;
    *(__nv_bfloat162*)(oh + (size_t)node * 128 + lane * 4 + 2) = h23;
    *(__nv_bfloat162*)(ol + (size_t)node * 128 + lane * 4) =
        __floats2bfloat162_rn(o.x - __bfloat162float(h01.x), o.y - __bfloat162float(h01.y));
    *(__nv_bfloat162*)(ol + (size_t)node * 128 + lane * 4 + 2) =
        __floats2bfloat162_rn(o.z - __bfloat162float(h23.x), o.w - __bfloat162float(h23.y));
}

// ----------- transpose + split: in[k][128 d][128 e] -> out[(k*128+e)][d] -----
__global__ void tsplit_kern(const float* __restrict__ in, __nv_bfloat16* __restrict__ oh,
                            __nv_bfloat16* __restrict__ ol) {
    __shared__ float ts[32][33];
    int k = blockIdx.z;
    int e0 = blockIdx.x * 32, d0 = blockIdx.y * 32;
    int tx = threadIdx.x, ty = threadIdx.y;
    const float* ink = in + (size_t)k * 16384;
#pragma unroll
    for (int j = 0; j < 32; j += 8)
        ts[ty + j][tx] = ink[(size_t)(d0 + ty + j) * 128 + e0 + tx];
    __syncthreads();
#pragma unroll
    for (int j = 0; j < 32; j += 8) {
        float v = ts[tx][ty + j];  // d = d0+tx, e = e0+ty+j
        size_t o = ((size_t)k * 128 + e0 + ty + j) * 128 + d0 + tx;
        __nv_bfloat16 h = __float2bfloat16(v);
        oh[o] = h;
        ol[o] = __float2bfloat16(v - __bfloat162float(h));
    }
}

// ===================== generic split-bf16 HMMA GEMM ==========================
// C[m,n] = sum_d A[m,d]*B[n,d], K=128. CTA 128x128, 8 warps (4x2), warp 32x64.
// EPI 0: write f32 to outF (ld = ldC). EPI 1: scatter split-bf16 qW layout.
#define HG_AH 0
#define HG_AL 34816
#define HG_BH 69632
#define HG_BL 104448
#define HG_SMEM 139264

template<int EPI>
__global__ __launch_bounds__(256, 1) void hmma_gemm(
    const __nv_bfloat16* __restrict__ Ah, const __nv_bfloat16* __restrict__ Al,
    const __nv_bfloat16* __restrict__ Bh, const __nv_bfloat16* __restrict__ Bl,
    float* __restrict__ outF, __nv_bfloat16* __restrict__ oh,
    __nv_bfloat16* __restrict__ ol, int ldC) {
    extern __shared__ char smem[];
    const int tid = threadIdx.x;
    const int warp = tid >> 5, lane = tid & 31;
    const int mt0 = blockIdx.y * 128, nt0 = blockIdx.x * 128;
    __nv_bfloat16* sAh = (__nv_bfloat16*)(smem + HG_AH);
    __nv_bfloat16* sAl = (__nv_bfloat16*)(smem + HG_AL);
    __nv_bfloat16* sBh = (__nv_bfloat16*)(smem + HG_BH);
    __nv_bfloat16* sBl = (__nv_bfloat16*)(smem + HG_BL);

    for (int i = tid; i < 2048; i += 256) {
        int row = i >> 4, c8 = (i & 15) << 3;
        size_t g = ((size_t)(mt0 + row)) * 128 + c8;
        *(uint4*)(sAh + row * 136 + c8) = *(const uint4*)(Ah + g);
        *(uint4*)(sAl + row * 136 + c8) = *(const uint4*)(Al + g);
        size_t gb = ((size_t)(nt0 + row)) * 128 + c8;
        *(uint4*)(sBh + row * 136 + c8) = *(const uint4*)(Bh + gb);
        *(uint4*)(sBl + row * 136 + c8) = *(const uint4*)(Bl + gb);
    }
    __syncthreads();

    const int wy = warp >> 1, wx = warp & 1;
    uint32_t sa_h = smem_u32(sAh) + ((wy * 32 + (lane & 15)) * 136 + ((lane & 16) ? 8 : 0)) * 2;
    uint32_t sa_l = sa_h + (HG_AL - HG_AH);
    uint32_t sb_h = smem_u32(sBh) + ((wx * 64 + (lane & 7)) * 136 + ((lane & 8) ? 8 : 0)) * 2;
    uint32_t sb_l = sb_h + (HG_BL - HG_BH);

    float acc[2][8][4];
#pragma unroll
    for (int mt = 0; mt < 2; mt++)
#pragma unroll
        for (int ch = 0; ch < 8; ch++)
#pragma unroll
            for (int j = 0; j < 4; j++) acc[mt][ch][j] = 0.f;

#pragma unroll
    for (int s = 0; s < 8; s++) {
        uint32_t RAh[2][4], RAl[2][4];
        LDSM_X4(RAh[0], sa_h + s * 32);
        LDSM_X4(RAh[1], sa_h + 4352 + s * 32);   // +16 rows * 272B
        LDSM_X4(RAl[0], sa_l + s * 32);
        LDSM_X4(RAl[1], sa_l + 4352 + s * 32);
#pragma unroll
        for (int ch = 0; ch < 8; ch++) {
            uint32_t RBh[2], RBl[2];
            LDSM_X2(RBh, sb_h + ch * 2176 + s * 32);
            LDSM_X2(RBl, sb_l + ch * 2176 + s * 32);
#pragma unroll
            for (int mt = 0; mt < 2; mt++) {
                MMA16816(acc[mt][ch], RAh[mt], RBh);
                MMA16816(acc[mt][ch], RAh[mt], RBl);
                MMA16816(acc[mt][ch], RAl[mt], RBh);
            }
        }
    }

    const int g = lane >> 2, t2 = lane & 3;
#pragma unroll
    for (int mt = 0; mt < 2; mt++) {
#pragma unroll
        for (int ch = 0; ch < 8; ch++) {
            int r = mt0 + wy * 32 + mt * 16 + g;
            int c = nt0 + wx * 64 + ch * 8 + t2 * 2;
            if (EPI == 0) {
                *(float2*)(outF + (size_t)r * ldC + c) =
                    make_float2(acc[mt][ch][0], acc[mt][ch][1]);
                *(float2*)(outF + (size_t)(r + 8) * ldC + c) =
                    make_float2(acc[mt][ch][2], acc[mt][ch][3]);
            } else {
                int kk = c >> 7, e = c & 127;
#pragma unroll
                for (int half = 0; half < 2; half++) {
                    int rr = r + half * 8;
                    int bb = rr >> 5, q = rr & 31;
                    size_t orow = ((size_t)bb * 512 + q * 16 + kk) * 128 + e;
                    float v0 = acc[mt][ch][half * 2], v1 = acc[mt][ch][half * 2 + 1];
                    __nv_bfloat162 ph = __floats2bfloat162_rn(v0, v1);
                    *(__nv_bfloat162*)(oh + orow) = ph;
                    *(__nv_bfloat162*)(ol + orow) = __floats2bfloat162_rn(
                        v0 - __bfloat162float(ph.x), v1 - __bfloat162float(ph.y));
                }
            }
        }
    }
}

// ----------- attention scores via HMMA: raw S[b,q,n] (scaled in softmax) -----
#define SC_AH 0
#define SC_AL 8704
#define SC_BH 17408
#define SC_BL 52224
#define SC_SMEM 87040
__global__ __launch_bounds__(256, 2) void score_hmma(
    const __nv_bfloat16* __restrict__ Qh, const __nv_bfloat16* __restrict__ Ql,
    const __nv_bfloat16* __restrict__ Dh, const __nv_bfloat16* __restrict__ Dl,
    float* __restrict__ S) {
    extern __shared__ char smem[];
    const int tid = threadIdx.x;
    const int warp = tid >> 5, lane = tid & 31;
    const int b = blockIdx.y, nt0 = blockIdx.x * 128;
    __nv_bfloat16* sAh = (__nv_bfloat16*)(smem + SC_AH);
    __nv_bfloat16* sAl = (__nv_bfloat16*)(smem + SC_AL);
    __nv_bfloat16* sBh = (__nv_bfloat16*)(smem + SC_BH);
    __nv_bfloat16* sBl = (__nv_bfloat16*)(smem + SC_BL);

    for (int i = tid; i < 512; i += 256) {
        int row = i >> 4, c8 = (i & 15) << 3;
        size_t g = ((size_t)b * 32 + row) * 128 + c8;
        *(uint4*)(sAh + row * 136 + c8) = *(const uint4*)(Qh + g);
        *(uint4*)(sAl + row * 136 + c8) = *(const uint4*)(Ql + g);
    }
    for (int i = tid; i < 2048; i += 256) {
        int row = i >> 4, c8 = (i & 15) << 3;
        size_t g = ((size_t)b * 512 + nt0 + row) * 128 + c8;
        *(uint4*)(sBh + row * 136 + c8) = *(const uint4*)(Dh + g);
        *(uint4*)(sBl + row * 136 + c8) = *(const uint4*)(Dl + g);
    }
    __syncthreads();

    uint32_t sa_h = smem_u32(sAh) + (((lane & 15)) * 136 + ((lane & 16) ? 8 : 0)) * 2;
    uint32_t sa_l = sa_h + (SC_AL - SC_AH);
    uint32_t sb_h = smem_u32(sBh) + ((warp * 16 + (lane & 7)) * 136 + ((lane & 8) ? 8 : 0)) * 2;
    uint32_t sb_l = sb_h + (SC_BL - SC_BH);

    float acc[2][2][4];
#pragma unroll
    for (int mt = 0; mt < 2; mt++)
#pragma unroll
        for (int ch = 0; ch < 2; ch++)
#pragma unroll
            for (int j = 0; j < 4; j++) acc[mt][ch][j] = 0.f;

#pragma unroll
    for (int s = 0; s < 8; s++) {
        uint32_t RAh[2][4], RAl[2][4];
        LDSM_X4(RAh[0], sa_h + s * 32);
        LDSM_X4(RAh[1], sa_h + 4352 + s * 32);
        LDSM_X4(RAl[0], sa_l + s * 32);
        LDSM_X4(RAl[1], sa_l + 4352 + s * 32);
#pragma unroll
        for (int ch = 0; ch < 2; ch++) {
            uint32_t RBh[2], RBl[2];
            LDSM_X2(RBh, sb_h + ch * 2176 + s * 32);
            LDSM_X2(RBl, sb_l + ch * 2176 + s * 32);
#pragma unroll
            for (int mt = 0; mt < 2; mt++) {
                MMA16816(acc[mt][ch], RAh[mt], RBh);
                MMA16816(acc[mt][ch], RAh[mt], RBl);
                MMA16816(acc[mt][ch], RAl[mt], RBh);
            }
        }
    }
    const int g = lane >> 2, t2 = lane & 3;
#pragma unroll
    for (int mt = 0; mt < 2; mt++)
#pragma unroll
        for (int ch = 0; ch < 2; ch++) {
            int r = mt * 16 + g;
            int n = nt0 + warp * 16 + ch * 8 + t2 * 2;
            *(float2*)(S + ((size_t)b * 32 + r) * 512 + n) =
                make_float2(acc[mt][ch][0], acc[mt][ch][1]);
            *(float2*)(S + ((size_t)b * 32 + r + 8) * 512 + n) =
                make_float2(acc[mt][ch][2], acc[mt][ch][3]);
        }
}

// ---------------- lq / ld : [nodes,128] @ VnT slice -> [nodes,16] ------------
__global__ __launch_bounds__(256) void lqld_kern(const float* __restrict__ feat,
                                                 const float* __restrict__ Vn, int off,
                                                 float* __restrict__ out) {
    __shared__ float sV[16 * 132];
    __shared__ float sf[64 * 132];
    const int n0 = blockIdx.x * 64;
    const int tid = threadIdx.x;
    for (int i = tid; i < 512; i += 256) {
        int k = i >> 5, d4 = i & 31;
        float4 v = *(const float4*)(Vn + k * 256 + off + d4 * 4);
        float* p = sV + k * 132 + d4 * 4;
        p[0] = v.x; p[1] = v.y; p[2] = v.z; p[3] = v.w;
    }
    for (int i = tid; i < 2048; i += 256) {
        int nn = i >> 5, d4 = i & 31;
        float4 v = *(const float4*)(feat + (size_t)(n0 + nn) * 128 + d4 * 4);
        float* p = sf + nn * 132 + d4 * 4;
        p[0] = v.x; p[1] = v.y; p[2] = v.z; p[3] = v.w;
    }
    __syncthreads();
    int node = tid >> 2, k0 = (tid & 3) * 4;
    float s0 = 0.f, s1 = 0.f, s2 = 0.f, s3 = 0.f;
#pragma unroll 4
    for (int d = 0; d < 128; d++) {
        float f = sf[node * 132 + d];
        s0 += f * sV[(k0 + 0) * 132 + d];
        s1 += f * sV[(k0 + 1) * 132 + d];
        s2 += f * sV[(k0 + 2) * 132 + d];
        s3 += f * sV[(k0 + 3) * 132 + d];
    }
    *(float4*)(out + (size_t)(n0 + node) * 16 + k0) = make_float4(s0, s1, s2, s3);
}

// ============ HMMA fused NTN level (split-bf16 mma.sync m16n8k16) ============
#define OFF_AH 0
#define OFF_AL 34816
#define OFF_BH 69632
#define OFF_BL 87040
#define OFF_LD 104448
#define OFF_LQ 108544
#define OFF_WK 109056
#define OFF_BN 109184
#define NTN_SMEM 109248

template<int HAS_B>
__global__ __launch_bounds__(256, 2) void ntn_hmma_kern(
    const __nv_bfloat16* __restrict__ Ah, const __nv_bfloat16* __restrict__ Al,
    const __nv_bfloat16* __restrict__ Bh, const __nv_bfloat16* __restrict__ Bl,
    const float* __restrict__ lq, const float* __restrict__ ld,
    const float* __restrict__ bn, const float* __restrict__ att,
    const float* __restrict__ wk,
    float* __restrict__ outA, float* __restrict__ outB) {
    extern __shared__ char smem[];
    const int tid = threadIdx.x;
    const int warp = tid >> 5, lane = tid & 31;
    const int b = blockIdx.z, mt = blockIdx.y, nt = blockIdx.x;

    __nv_bfloat16* sAh = (__nv_bfloat16*)(smem + OFF_AH);
    __nv_bfloat16* sAl = (__nv_bfloat16*)(smem + OFF_AL);
    __nv_bfloat16* sBh = (__nv_bfloat16*)(smem + OFF_BH);
    __nv_bfloat16* sBl = (__nv_bfloat16*)(smem + OFF_BL);
    float* s_ld = (float*)(smem + OFF_LD);
    float* s_lq = (float*)(smem + OFF_LQ);
    float* s_wk = (float*)(smem + OFF_WK);
    float* s_bn = (float*)(smem + OFF_BN);

    for (int i = tid; i < 2048; i += 256) {
        int row = i >> 4, c8 = (i & 15) << 3;
        size_t g = ((size_t)b * 512 + (size_t)mt * 128 + row) * 128 + c8;
        *(uint4*)(sAh + row * 136 + c8) = *(const uint4*)(Ah + g);
        *(uint4*)(sAl + row * 136 + c8) = *(const uint4*)(Al + g);
    }
    for (int i = tid; i < 1024; i += 256) {
        int row = i >> 4, c8 = (i & 15) << 3;
        size_t g = ((size_t)b * 512 + (size_t)nt * 64 + row) * 128 + c8;
        *(uint4*)(sBh + row * 136 + c8) = *(const uint4*)(Bh + g);
        *(uint4*)(sBl + row * 136 + c8) = *(const uint4*)(Bl + g);
    }
    for (int i = tid; i < 256; i += 256)
        ((float4*)s_ld)[i] = ((const float4*)(ld + ((size_t)b * 512 + (size_t)nt * 64) * 16))[i];
    if (tid < 128) s_lq[tid] = lq[((size_t)b * 32 + mt * 8) * 16 + tid];
    if (tid < 32) s_wk[tid] = wk[tid];
    if (tid < 16) s_bn[tid] = bn[tid];
    __syncthreads();

    const int m0 = warp * 16;
    uint32_t sa_h = smem_u32(sAh) + ((m0 + (lane & 15)) * 136 + ((lane & 16) ? 8 : 0)) * 2;
    uint32_t sa_l = sa_h + (OFF_BH - OFF_AL);
    uint32_t sb_h = smem_u32(sBh) + ((lane & 7) * 136 + ((lane & 8) ? 8 : 0)) * 2;
    uint32_t sb_l = sb_h + (OFF_LD - OFF_BL);

    float acc[8][4];
#pragma unroll
    for (int c = 0; c < 8; c++)
#pragma unroll
        for (int j = 0; j < 4; j++) acc[c][j] = 0.f;

#pragma unroll
    for (int s = 0; s < 8; s++) {
        uint32_t RAh[4], RAl[4];
        LDSM_X4(RAh, sa_h + s * 32);
        LDSM_X4(RAl, sa_l + s * 32);
#pragma unroll
        for (int ch = 0; ch < 8; ch++) {
            uint32_t RBh[2], RBl[2];
            LDSM_X2(RBh, sb_h + ch * 2176 + s * 32);
            LDSM_X2(RBl, sb_l + ch * 2176 + s * 32);
            MMA16816(acc[ch], RAh, RBh);
            MMA16816(acc[ch], RAh, RBl);
            MMA16816(acc[ch], RAl, RBh);
        }
    }

    const int q = mt * 8 + warp;
    const int k0 = lane >> 2;
    const int c2 = (lane & 3) * 2;
    const float lq0 = s_lq[warp * 16 + k0] + s_bn[k0];
    const float lq1 = s_lq[warp * 16 + k0 + 8] + s_bn[k0 + 8];
    const float al0 = s_wk[k0], al1 = s_wk[k0 + 8];
    const float be0 = HAS_B ? s_wk[16 + k0] : 0.f;
    const float be1 = HAS_B ? s_wk[16 + k0 + 8] : 0.f;

#pragma unroll
    for (int ch = 0; ch < 8; ch++) {
        int n0 = ch * 8 + c2;
        float sg00 = 1.f / (1.f + __expf(-(acc[ch][0] + lq0 + s_ld[n0 * 16 + k0])));
        float sg01 = 1.f / (1.f + __expf(-(acc[ch][1] + lq0 + s_ld[(n0 + 1) * 16 + k0])));
        float sg10 = 1.f / (1.f + __expf(-(acc[ch][2] + lq1 + s_ld[n0 * 16 + k0 + 8])));
        float sg11 = 1.f / (1.f + __expf(-(acc[ch][3] + lq1 + s_ld[(n0 + 1) * 16 + k0 + 8])));
        float u0 = al0 * sg00 + al1 * sg10;
        float u1 = al0 * sg01 + al1 * sg11;
        float v0 = 0.f, v1 = 0.f;
        if (HAS_B) { v0 = be0 * sg00 + be1 * sg10; v1 = be0 * sg01 + be1 * sg11; }
#pragma unroll
        for (int off = 4; off < 32; off <<= 1) {
            u0 += __shfl_xor_sync(0xffffffffu, u0, off);
            u1 += __shfl_xor_sync(0xffffffffu, u1, off);
            if (HAS_B) {
                v0 += __shfl_xor_sync(0xffffffffu, v0, off);
                v1 += __shfl_xor_sync(0xffffffffu, v1, off);
            }
        }
        if (lane < 4) {
            size_t o = ((size_t)b * 32 + q) * 512 + (size_t)nt * 64 + ch * 8 + lane * 2;
            float a0 = att[o], a1 = att[o + 1];
            outA[o]     = u0 * a0;
            outA[o + 1] = u1 * a1;
            if (HAS_B) {
                outB[o]     += v0 * a0;
                outB[o + 1] += v1 * a1;
            }
        }
    }
}

// ----------------------------- softmaxes -------------------------------------
__device__ __forceinline__ float warp_max(float v) {
#pragma unroll
    for (int o = 16; o > 0; o >>= 1) v = fmaxf(v, __shfl_xor_sync(0xffffffffu, v, o));
    return v;
}
__device__ __forceinline__ float warp_sum(float v) {
#pragma unroll
    for (int o = 16; o > 0; o >>= 1) v += __shfl_xor_sync(0xffffffffu, v, o);
    return v;
}

__global__ void row_softmax512(float* __restrict__ p, float scale) {
    int row = blockIdx.x * 8 + (threadIdx.x >> 5);
    int lane = threadIdx.x & 31;
    float* r = p + (size_t)row * 512 + lane * 16;
    float v[16];
#pragma unroll
    for (int j = 0; j < 4; j++) {
        float4 t = *(float4*)(r + j * 4);
        v[j*4+0]=t.x*scale; v[j*4+1]=t.y*scale; v[j*4+2]=t.z*scale; v[j*4+3]=t.w*scale;
    }
    float m = -1e30f;
#pragma unroll
    for (int i = 0; i < 16; i++) m = fmaxf(m, v[i]);
    m = warp_max(m);
    float s = 0.f;
#pragma unroll
    for (int i = 0; i < 16; i++) { v[i] = __expf(v[i] - m); s += v[i]; }
    s = warp_sum(s);
    float inv = 1.f / s;
#pragma unroll
    for (int j = 0; j < 4; j++)
        *(float4*)(r + j * 4) = make_float4(v[j*4+0]*inv, v[j*4+1]*inv, v[j*4+2]*inv, v[j*4+3]*inv);
}

__global__ void final_kern(const float* __restrict__ e1, const float* __restrict__ acc,
                           const float* __restrict__ e3, const float* __restrict__ wk,
                           float* __restrict__ out) {
    float w0 = wk[96], w2 = wk[97];
    int row = blockIdx.x * 8 + (threadIdx.x >> 5);
    int lane = threadIdx.x & 31;
    size_t base = (size_t)row * 512 + lane * 16;
    float v[16];
#pragma unroll
    for (int j = 0; j < 4; j++) {
        float4 a = *(const float4*)(e1 + base + j * 4);
        float4 b = *(const float4*)(acc + base + j * 4);
        float4 c = *(const float4*)(e3 + base + j * 4);
        v[j*4+0] = w0*a.x + b.x + w2*c.x;
        v[j*4+1] = w0*a.y + b.y + w2*c.y;
        v[j*4+2] = w0*a.z + b.z + w2*c.z;
        v[j*4+3] = w0*a.w + b.w + w2*c.w;
    }
    float m = -1e30f;
#pragma unroll
    for (int i = 0; i < 16; i++) m = fmaxf(m, v[i]);
    m = warp_max(m);
    float s = 0.f;
#pragma unroll
    for (int i = 0; i < 16; i++) { v[i] = __expf(v[i] - m); s += v[i]; }
    s = warp_sum(s);
    float inv = 1.f / s;
#pragma unroll
    for (int j = 0; j < 4; j++)
        *(float4*)(out + base + j * 4) =
            make_float4(v[j*4+0]*inv, v[j*4+1]*inv, v[j*4+2]*inv, v[j*4+3]*inv);
}

// -------------------- folded weight preparation ------------------------------
__global__ void prep_wk(const float* __restrict__ cw1, const float* __restrict__ cw2,
                        const float* __restrict__ cw3, const float* __restrict__ w_end,
                        float* __restrict__ wk) {
    int k = threadIdx.x;
    if (k < 16) {
        wk[k]      = cw1[k];                              wk[16 + k] = 0.f;
        wk[32 + k] = w_end[1] * cw2[k] + w_end[19 + k];   wk[48 + k] = 0.f;
        wk[64 + k] = cw3[k];
        wk[80 + k] = w_end[3 + k] + w_end[35 + k];
    }
    if (k == 0) { wk[96] = w_end[0]; wk[97] = w_end[2]; }
}

// ------------------------------- host side -----------------------------------
static inline void* symaddr(const void* sym) {
    void* p = nullptr;
    cudaGetSymbolAddress(&p, sym);
    return p;
}

extern "C" void kernel_launch(void* const* d_in, const int* in_sizes, int n_in,
                              void* d_out, int out_size) {
    const float *x_d, *x_q;
    const int *ei_d, *ei_q;
    if (in_sizes[1] == 2 * EDM) {
        x_d = (const float*)d_in[0]; ei_d = (const int*)d_in[1];
        x_q = (const float*)d_in[2]; ei_q = (const int*)d_in[3];
    } else {
        x_d = (const float*)d_in[0]; x_q = (const float*)d_in[1];
        ei_d = (const int*)d_in[2]; ei_q = (const int*)d_in[3];
    }
    const float* W1 = (const float*)d_in[6];  const float* b1 = (const float*)d_in[7];
    const float* W2 = (const float*)d_in[8];  const float* b2 = (const float*)d_in[9];
    const float* W3 = (const float*)d_in[10]; const float* b3 = (const float*)d_in[11];
    const float* Wn[3] = {(const float*)d_in[12], (const float*)d_in[17], (const float*)d_in[22]};
    const float* Vn[3] = {(const float*)d_in[13], (const float*)d_in[18], (const float*)d_in[23]};
    const float* bn[3] = {(const float*)d_in[14], (const float*)d_in[19], (const float*)d_in[24]};
    const float* cw1 = (const float*)d_in[15];
    const float* cw2 = (const float*)d_in[20];
    const float* cw3 = (const float*)d_in[25];
    const float* w_end = (const float*)d_in[27];

    cudaFuncSetAttribute(hmma_gemm<0>, cudaFuncAttributeMaxDynamicSharedMemorySize, HG_SMEM);
    cudaFuncSetAttribute(hmma_gemm<1>, cudaFuncAttributeMaxDynamicSharedMemorySize, HG_SMEM);
    cudaFuncSetAttribute(score_hmma,   cudaFuncAttributeMaxDynamicSharedMemorySize, SC_SMEM);
    cudaFuncSetAttribute(ntn_hmma_kern<0>, cudaFuncAttributeMaxDynamicSharedMemorySize, NTN_SMEM);
    cudaFuncSetAttribute(ntn_hmma_kern<1>, cudaFuncAttributeMaxDynamicSharedMemorySize, NTN_SMEM);

    float* p_dinv_d = (float*)symaddr(g_dinv_d); float* p_dinv_q = (float*)symaddr(g_dinv_q);
    int* p_indeg_d = (int*)symaddr(g_indeg_d);   int* p_indeg_q = (int*)symaddr(g_indeg_q);
    int* p_rows_d = (int*)symaddr(g_rows_d);     int* p_rows_q = (int*)symaddr(g_rows_q);
    int* p_fill_d = (int*)symaddr(g_fill_d);     int* p_fill_q = (int*)symaddr(g_fill_q);
    int* p_cols_d = (int*)symaddr(g_cols_d);     int* p_cols_q = (int*)symaddr(g_cols_q);
    float* p_vals_d = (float*)symaddr(g_vals_d); float* p_vals_q = (float*)symaddr(g_vals_q);
    float* p_xw = (float*)symaddr(g_xw);
    float* p_hd = (float*)symaddr(g_hd);         float* p_hq = (float*)symaddr(g_hq);
    float* p_att = (float*)symaddr(g_att);
    float* p_lq = (float*)symaddr(g_lq);         float* p_ld = (float*)symaddr(g_ld);
    float* p_e1 = (float*)symaddr(g_e1);         float* p_e3 = (float*)symaddr(g_e3);
    float* p_acc = (float*)symaddr(g_acc);       float* p_wk = (float*)symaddr(g_wk);
    __nv_bfloat16* p_hdh = (__nv_bfloat16*)symaddr(g_hdh);
    __nv_bfloat16* p_hdl = (__nv_bfloat16*)symaddr(g_hdl);
    __nv_bfloat16* p_hqh = (__nv_bfloat16*)symaddr(g_hqh);
    __nv_bfloat16* p_hql = (__nv_bfloat16*)symaddr(g_hql);
    __nv_bfloat16* p_qwh = (__nv_bfloat16*)symaddr(g_qwh);
    __nv_bfloat16* p_qwl = (__nv_bfloat16*)symaddr(g_qwl);
    __nv_bfloat16* p_w2th = (__nv_bfloat16*)symaddr(g_w2th);
    __nv_bfloat16* p_w2tl = (__nv_bfloat16*)symaddr(g_w2tl);
    __nv_bfloat16* p_w3th = (__nv_bfloat16*)symaddr(g_w3th);
    __nv_bfloat16* p_w3tl = (__nv_bfloat16*)symaddr(g_w3tl);
    __nv_bfloat16* p_wnth = (__nv_bfloat16*)symaddr(g_wnth);
    __nv_bfloat16* p_wntl = (__nv_bfloat16*)symaddr(g_wntl);
    float* out = (float*)d_out;

    const int* src_d = ei_d;           const int* dst_d = ei_d + EDM;
    const int* src_q = ei_q;           const int* dst_q = ei_q + EQM;

    prep_wk<<<1, 32>>>(cw1, cw2, cw3, w_end, p_wk);

    // ---- weight transposes + splits ----
    tsplit_kern<<<dim3(4, 4, 1), dim3(32, 8)>>>(W2, p_w2th, p_w2tl);
    tsplit_kern<<<dim3(4, 4, 1), dim3(32, 8)>>>(W3, p_w3th, p_w3tl);
    for (int l = 0; l < 3; l++)
        tsplit_kern<<<dim3(4, 4, 16), dim3(32, 8)>>>(Wn[l], p_wnth + (size_t)l * 2048 * 128,
                                                     p_wntl + (size_t)l * 2048 * 128);

    // ---- CSR build ----
    zero2_kern<<<(NDN + 255) / 256, 256>>>(p_indeg_d, p_fill_d, NDN);
    zero2_kern<<<(NQN + 255) / 256, 256>>>(p_indeg_q, p_fill_q, NQN);
    count_deg_kern<<<EDM / 256, 256>>>(dst_d, EDM, p_indeg_d);
    count_deg_kern<<<EQM / 256, 256>>>(dst_q, EQM, p_indeg_q);
    dinv_kern<<<(NDN + 255) / 256, 256>>>(p_indeg_d, p_dinv_d, NDN);
    dinv_kern<<<(NQN + 255) / 256, 256>>>(p_indeg_q, p_dinv_q, NQN);
    scan_csr_kern<<<BBATCH, 512>>>(p_indeg_d, p_rows_d, NDD, NDD * 8);
    scan_csr_kern<<<BBATCH, 32>>>(p_indeg_q, p_rows_q, NQD, NQD * 8);
    fill_csr_kern<<<EDM / 256, 256>>>(src_d, dst_d, EDM, p_dinv_d, p_rows_d, p_fill_d, p_cols_d, p_vals_d);
    fill_csr_kern<<<EQM / 256, 256>>>(src_q, dst_q, EQM, p_dinv_q, p_rows_q, p_fill_q, p_cols_q, p_vals_q);

    // ---- 3-layer GCN, data side ----
    sgemm_xw<<<NDN / 128, 256>>>(x_d, W1, p_xw, DINF);
    spmm_gcn<<<NDN * 32 / 256, 256>>>(p_xw, p_rows_d, p_cols_d, p_vals_d, p_indeg_d, p_dinv_d, b1,
                                      p_hd, p_hdh, p_hdl, NDN);
    hmma_gemm<0><<<dim3(1, 256), 256, HG_SMEM>>>(p_hdh, p_hdl, p_w2th, p_w2tl, p_xw, nullptr, nullptr, 128);
    spmm_gcn<<<NDN * 32 / 256, 256>>>(p_xw, p_rows_d, p_cols_d, p_vals_d, p_indeg_d, p_dinv_d, b2,
                                      p_hd + (size_t)NDN * DDF, p_hdh + (size_t)NDN * DDF,
                                      p_hdl + (size_t)NDN * DDF, NDN);
    hmma_gemm<0><<<dim3(1, 256), 256, HG_SMEM>>>(p_hdh + (size_t)NDN * DDF, p_hdl + (size_t)NDN * DDF,
                                                 p_w3th, p_w3tl, p_xw, nullptr, nullptr, 128);
    spmm_gcn<<<NDN * 32 / 256, 256>>>(p_xw, p_rows_d, p_cols_d, p_vals_d, p_indeg_d, p_dinv_d, b3,
                                      p_hd + (size_t)2 * NDN * DDF, p_hdh + (size_t)2 * NDN * DDF,
                                      p_hdl + (size_t)2 * NDN * DDF, NDN);

    // ---- 3-layer GCN, query side ----
    sgemm_xw<<<NQN / 128, 256>>>(x_q, W1, p_xw, DINF);
    spmm_gcn<<<NQN * 32 / 256, 256>>>(p_xw, p_rows_q, p_cols_q, p_vals_q, p_indeg_q, p_dinv_q, b1,
                                      p_hq, p_hqh, p_hql, NQN);
    hmma_gemm<0><<<dim3(1, 16), 256, HG_SMEM>>>(p_hqh, p_hql, p_w2th, p_w2tl, p_xw, nullptr, nullptr, 128);
    spmm_gcn<<<NQN * 32 / 256, 256>>>(p_xw, p_rows_q, p_cols_q, p_vals_q, p_indeg_q, p_dinv_q, b2,
                                      p_hq + (size_t)NQN * DDF, p_hqh + (size_t)NQN * DDF,
                                      p_hql + (size_t)NQN * DDF, NQN);
    hmma_gemm<0><<<dim3(1, 16), 256, HG_SMEM>>>(p_hqh + (size_t)NQN * DDF, p_hql + (size_t)NQN * DDF,
                                                p_w3th, p_w3tl, p_xw, nullptr, nullptr, 128);
    spmm_gcn<<<NQN * 32 / 256, 256>>>(p_xw, p_rows_q, p_cols_q, p_vals_q, p_indeg_q, p_dinv_q, b3,
                                      p_hq + (size_t)2 * NQN * DDF, p_hqh + (size_t)2 * NQN * DDF,
                                      p_hql + (size_t)2 * NQN * DDF, NQN);

    // ---- three attention/NTN levels ----
    for (int l = 0; l < 3; l++) {
        const __nv_bfloat16* qh = p_hqh + (size_t)l * NQN * DDF;
        const __nv_bfloat16* ql = p_hql + (size_t)l * NQN * DDF;
        const __nv_bfloat16* dh = p_hdh + (size_t)l * NDN * DDF;
        const __nv_bfloat16* dl = p_hdl + (size_t)l * NDN * DDF;
        const float* qf = p_hq + (size_t)l * NQN * DDF;
        const float* df = p_hd + (size_t)l * NDN * DDF;

        score_hmma<<<dim3(4, BBATCH), 256, SC_SMEM>>>(qh, ql, dh, dl, p_att);
        row_softmax512<<<256, 256>>>(p_att, 0.08838834764831845f);
        hmma_gemm<1><<<dim3(16, 16), 256, HG_SMEM>>>(qh, ql,
            p_wnth + (size_t)l * 2048 * 128, p_wntl + (size_t)l * 2048 * 128,
            nullptr, p_qwh, p_qwl, 0);
        lqld_kern<<<NQN / 64, 256>>>(qf, Vn[l], 0, p_lq);
        lqld_kern<<<NDN / 64, 256>>>(df, Vn[l], DDF, p_ld);
        if (l == 0)
            ntn_hmma_kern<0><<<dim3(8, 4, BBATCH), 256, NTN_SMEM>>>(
                p_qwh, p_qwl, dh, dl, p_lq, p_ld, bn[l], p_att, p_wk, p_e1, nullptr);
        else if (l == 1)
            ntn_hmma_kern<0><<<dim3(8, 4, BBATCH), 256, NTN_SMEM>>>(
                p_qwh, p_qwl, dh, dl, p_lq, p_ld, bn[l], p_att, p_wk + 32, p_acc, nullptr);
        else
            ntn_hmma_kern<1><<<dim3(8, 4, BBATCH), 256, NTN_SMEM>>>(
                p_qwh, p_qwl, dh, dl, p_lq, p_ld, bn[l], p_att, p_wk + 64, p_e3, p_acc);
    }

    // ---- softmaxes + final combine ----
    row_softmax512<<<256, 256>>>(p_e1, 1.0f);
    row_softmax512<<<256, 256>>>(p_e3, 1.0f);
    final_kern<<<256, 256>>>(p_e1, p_acc, p_e3, p_wk, out);
}